// round 1
// baseline (speedup 1.0000x reference)
#include <cuda_runtime.h>
#include <math.h>

#define H     768
#define IDIM  3072
#define NE    16
#define NS    2
#define NEXP  (NE + NS)          // 18 expert slots (16 routed + 2 shared)
#define NTOK  2048
#define KSEL  2
#define NPAIR (NTOK * 4)         // 2 routed + 2 shared pairs per token = 8192
#define ROUTED_PAIRS (NTOK * KSEL)

// ---------------- scratch (static device globals; no allocation) ----------------
__device__ float d_act[(size_t)NPAIR * IDIM];   // ~100.7 MB: silu(g)*u per pair
__device__ float d_y[(size_t)NPAIR * H];        // ~25.2 MB: down-proj per pair
__device__ int   d_pair_token[NPAIR];
__device__ float d_pair_weight[NPAIR];
__device__ int   d_token_pair[NTOK * 4];
__device__ int   d_cnt[NE];
__device__ int   d_fill[NE];
__device__ int   d_off[NEXP + 1];
__device__ int   d_tok_e[NTOK * KSEL];
__device__ float d_tok_w[NTOK * KSEL];

// ---------------- init ----------------
__global__ void init_kernel() {
    int t = threadIdx.x;
    if (t < NE) { d_cnt[t] = 0; d_fill[t] = 0; }
}

// ---------------- router: one warp per token ----------------
__global__ __launch_bounds__(256) void router_kernel(const float* __restrict__ x,
                                                     const float* __restrict__ gw) {
    int warp = (blockIdx.x * blockDim.x + threadIdx.x) >> 5;
    int lane = threadIdx.x & 31;
    if (warp >= NTOK) return;
    const float* xr = x + (size_t)warp * H;

    float acc[NE];
#pragma unroll
    for (int e = 0; e < NE; e++) acc[e] = 0.f;

    for (int h = lane; h < H; h += 32) {
        float xv = xr[h];
#pragma unroll
        for (int e = 0; e < NE; e++) acc[e] += xv * gw[e * H + h];
    }
#pragma unroll
    for (int e = 0; e < NE; e++) {
#pragma unroll
        for (int o = 16; o > 0; o >>= 1) acc[e] += __shfl_xor_sync(0xFFFFFFFFu, acc[e], o);
    }

    if (lane == 0) {
        // softmax
        float mx = acc[0];
#pragma unroll
        for (int e = 1; e < NE; e++) mx = fmaxf(mx, acc[e]);
        float p[NE]; float s = 0.f;
#pragma unroll
        for (int e = 0; e < NE; e++) { p[e] = expf(acc[e] - mx); s += p[e]; }
        float inv = 1.f / s;
#pragma unroll
        for (int e = 0; e < NE; e++) p[e] *= inv;   // probabilities

        // top-2 (first occurrence wins on ties, matching lax.top_k)
        int e0 = 0; float w0 = p[0];
        int e1 = -1; float w1 = -1.f;
#pragma unroll
        for (int e = 1; e < NE; e++) {
            if (p[e] > w0) { e1 = e0; w1 = w0; e0 = e; w0 = p[e]; }
            else if (p[e] > w1) { e1 = e; w1 = p[e]; }
        }
        float denom = w0 + w1 + 1e-8f;
        float rw0 = w0 / denom;   // SCALE = 1.0
        float rw1 = w1 / denom;

        d_tok_e[warp * 2 + 0] = e0;  d_tok_w[warp * 2 + 0] = rw0;
        d_tok_e[warp * 2 + 1] = e1;  d_tok_w[warp * 2 + 1] = rw1;
        atomicAdd(&d_cnt[e0], 1);
        atomicAdd(&d_cnt[e1], 1);
    }
}

// ---------------- offsets (serial, 16 elements) ----------------
__global__ void scan_kernel() {
    if (threadIdx.x == 0) {
        int acc = 0;
        for (int e = 0; e < NE; e++) { d_off[e] = acc; acc += d_cnt[e]; }
        d_off[NE]     = ROUTED_PAIRS;            // == acc
        d_off[NE + 1] = ROUTED_PAIRS + NTOK;     // shared expert 0 segment
        d_off[NE + 2] = ROUTED_PAIRS + 2 * NTOK; // shared expert 1 segment
    }
}

// ---------------- build pair lists ----------------
__global__ void build_pairs_kernel() {
    int t = blockIdx.x * blockDim.x + threadIdx.x;
    if (t >= NTOK) return;
#pragma unroll
    for (int k = 0; k < KSEL; k++) {
        int e = d_tok_e[t * 2 + k];
        float w = d_tok_w[t * 2 + k];
        int pos = d_off[e] + atomicAdd(&d_fill[e], 1);
        d_pair_token[pos] = t;
        d_pair_weight[pos] = w;
        d_token_pair[t * 4 + k] = pos;
    }
#pragma unroll
    for (int s = 0; s < NS; s++) {
        int pos = ROUTED_PAIRS + s * NTOK + t;
        d_pair_token[pos] = t;
        d_pair_weight[pos] = 0.5f;               // mean over S=2 shared experts
        d_token_pair[t * 4 + 2 + s] = pos;
    }
}

// ---------------- fused up/gate GEMM + SiLU: act[p,i] = silu(x@wg) * (x@wu) ----------------
// tile: BM=64, BN=64, BK=16; 256 threads, 4x4 per thread, two accumulators (g,u)
#define BM 64
#define BN 64
#define BK 16

__global__ __launch_bounds__(256) void up_act_kernel(const float* __restrict__ x,
                                                     const float* __restrict__ wg,
                                                     const float* __restrict__ wu,
                                                     const float* __restrict__ swg,
                                                     const float* __restrict__ swu) {
    int ez  = blockIdx.z;
    int off = d_off[ez];
    int cnt = d_off[ez + 1] - off;
    int m0  = blockIdx.y * BM;
    if (m0 >= cnt) return;
    int n0  = blockIdx.x * BN;

    const float* Bg; const float* Bu;
    if (ez < NE) { Bg = wg + (size_t)ez * H * IDIM;        Bu = wu + (size_t)ez * H * IDIM; }
    else         { Bg = swg + (size_t)(ez - NE) * H * IDIM; Bu = swu + (size_t)(ez - NE) * H * IDIM; }

    __shared__ float As[BM][BK + 1];
    __shared__ float Bgs[BK][BN];
    __shared__ float Bus[BK][BN];
    __shared__ int   toks[BM];

    int tid = threadIdx.x;
    if (tid < BM) {
        int m = m0 + tid; if (m >= cnt) m = cnt - 1;
        toks[tid] = d_pair_token[off + m];
    }
    __syncthreads();

    float cg[4][4] = {}, cu[4][4] = {};
    int tx = tid & 15, ty = tid >> 4;

    int a_m  = tid >> 2;            // 0..63
    int a_k4 = (tid & 3) * 4;       // 0,4,8,12
    int b_n4 = (tid & 15) * 4;      // 0..60
    int b_k  = tid >> 4;            // 0..15

    for (int k0 = 0; k0 < H; k0 += BK) {
        // A: gathered token rows, float4 loads
        {
            float4 v = *(const float4*)(x + (size_t)toks[a_m] * H + k0 + a_k4);
            As[a_m][a_k4 + 0] = v.x; As[a_m][a_k4 + 1] = v.y;
            As[a_m][a_k4 + 2] = v.z; As[a_m][a_k4 + 3] = v.w;
        }
        // B: wg and wu tiles, float4 loads
        {
            size_t boff = (size_t)(k0 + b_k) * IDIM + n0 + b_n4;
            *(float4*)&Bgs[b_k][b_n4] = *(const float4*)(Bg + boff);
            *(float4*)&Bus[b_k][b_n4] = *(const float4*)(Bu + boff);
        }
        __syncthreads();
#pragma unroll
        for (int k = 0; k < BK; k++) {
            float a[4];
#pragma unroll
            for (int i = 0; i < 4; i++) a[i] = As[ty * 4 + i][k];
            float4 bg = *(const float4*)&Bgs[k][tx * 4];
            float4 bu = *(const float4*)&Bus[k][tx * 4];
            float bgv[4] = {bg.x, bg.y, bg.z, bg.w};
            float buv[4] = {bu.x, bu.y, bu.z, bu.w};
#pragma unroll
            for (int i = 0; i < 4; i++)
#pragma unroll
                for (int j = 0; j < 4; j++) {
                    cg[i][j] += a[i] * bgv[j];
                    cu[i][j] += a[i] * buv[j];
                }
        }
        __syncthreads();
    }

#pragma unroll
    for (int i = 0; i < 4; i++) {
        int m = m0 + ty * 4 + i;
        if (m < cnt) {
            size_t row = (size_t)(off + m) * IDIM + n0 + tx * 4;
#pragma unroll
            for (int j = 0; j < 4; j++) {
                float g = cg[i][j];
                float u = cu[i][j];
                d_act[row + j] = (g / (1.f + expf(-g))) * u;
            }
        }
    }
}

// ---------------- down GEMM: y[p,h] = act[p,:] @ wd_e ----------------
__global__ __launch_bounds__(256) void down_kernel(const float* __restrict__ wd,
                                                   const float* __restrict__ swd) {
    int ez  = blockIdx.z;
    int off = d_off[ez];
    int cnt = d_off[ez + 1] - off;
    int m0  = blockIdx.y * BM;
    if (m0 >= cnt) return;
    int n0  = blockIdx.x * BN;

    const float* B = (ez < NE) ? (wd + (size_t)ez * IDIM * H)
                               : (swd + (size_t)(ez - NE) * IDIM * H);

    __shared__ float As[BM][BK + 1];
    __shared__ float Bs[BK][BN];

    int tid = threadIdx.x;
    float c[4][4] = {};
    int tx = tid & 15, ty = tid >> 4;

    int a_m  = tid >> 2;
    int a_k4 = (tid & 3) * 4;
    int b_n4 = (tid & 15) * 4;
    int b_k  = tid >> 4;

    int am_clamped = m0 + a_m; if (am_clamped >= cnt) am_clamped = cnt - 1;
    const float* arow = d_act + (size_t)(off + am_clamped) * IDIM;

    for (int k0 = 0; k0 < IDIM; k0 += BK) {
        {
            float4 v = *(const float4*)(arow + k0 + a_k4);
            As[a_m][a_k4 + 0] = v.x; As[a_m][a_k4 + 1] = v.y;
            As[a_m][a_k4 + 2] = v.z; As[a_m][a_k4 + 3] = v.w;
        }
        {
            size_t boff = (size_t)(k0 + b_k) * H + n0 + b_n4;
            *(float4*)&Bs[b_k][b_n4] = *(const float4*)(B + boff);
        }
        __syncthreads();
#pragma unroll
        for (int k = 0; k < BK; k++) {
            float a[4];
#pragma unroll
            for (int i = 0; i < 4; i++) a[i] = As[ty * 4 + i][k];
            float4 b4 = *(const float4*)&Bs[k][tx * 4];
            float bv[4] = {b4.x, b4.y, b4.z, b4.w};
#pragma unroll
            for (int i = 0; i < 4; i++)
#pragma unroll
                for (int j = 0; j < 4; j++)
                    c[i][j] += a[i] * bv[j];
        }
        __syncthreads();
    }

#pragma unroll
    for (int i = 0; i < 4; i++) {
        int m = m0 + ty * 4 + i;
        if (m < cnt) {
            size_t row = (size_t)(off + m) * H + n0 + tx * 4;
#pragma unroll
            for (int j = 0; j < 4; j++) d_y[row + j] = c[i][j];
        }
    }
}

// ---------------- combine: out[t,:] = sum_j w_j * y[pair_j,:] (fixed order -> deterministic) ----------------
__global__ __launch_bounds__(256) void combine_kernel(float* __restrict__ out) {
    int t = blockIdx.x;
    int p0 = d_token_pair[t * 4 + 0], p1 = d_token_pair[t * 4 + 1];
    int p2 = d_token_pair[t * 4 + 2], p3 = d_token_pair[t * 4 + 3];
    float w0 = d_pair_weight[p0], w1 = d_pair_weight[p1];
    float w2 = d_pair_weight[p2], w3 = d_pair_weight[p3];
    const float* y0 = d_y + (size_t)p0 * H;
    const float* y1 = d_y + (size_t)p1 * H;
    const float* y2 = d_y + (size_t)p2 * H;
    const float* y3 = d_y + (size_t)p3 * H;
    float* o = out + (size_t)t * H;
    for (int h = threadIdx.x; h < H; h += blockDim.x)
        o[h] = w0 * y0[h] + w1 * y1[h] + w2 * y2[h] + w3 * y3[h];
}

// ---------------- launch ----------------
extern "C" void kernel_launch(void* const* d_in, const int* in_sizes, int n_in,
                              void* d_out, int out_size) {
    const float* x      = (const float*)d_in[0];
    const float* gate_w = (const float*)d_in[1];
    const float* swg    = (const float*)d_in[2];
    const float* swu    = (const float*)d_in[3];
    const float* swd    = (const float*)d_in[4];
    const float* wg     = (const float*)d_in[5];
    const float* wu     = (const float*)d_in[6];
    const float* wd     = (const float*)d_in[7];
    float* out = (float*)d_out;

    init_kernel<<<1, 32>>>();
    router_kernel<<<NTOK / 8, 256>>>(x, gate_w);       // 8 warps (tokens) / block
    scan_kernel<<<1, 32>>>();
    build_pairs_kernel<<<NTOK / 256, 256>>>();

    dim3 gUp(IDIM / BN, NTOK / BM, NEXP);              // (48, 32, 18); blocks beyond count exit
    up_act_kernel<<<gUp, 256>>>(x, wg, wu, swg, swu);

    dim3 gDown(H / BN, NTOK / BM, NEXP);               // (12, 32, 18)
    down_kernel<<<gDown, 256>>>(wd, swd);

    combine_kernel<<<NTOK, 256>>>(out);
}

// round 3
// speedup vs baseline: 1.3090x; 1.3090x over previous
#include <cuda_runtime.h>
#include <cuda_bf16.h>
#include <mma.h>
#include <math.h>
#include <stdint.h>

using namespace nvcuda;

#define H     768
#define IDIM  3072
#define NE    16
#define NS    2
#define NEXP  (NE + NS)
#define NTOK  2048
#define KSEL  2
#define NPAIR (NTOK * 4)
#define ROUTED_PAIRS (NTOK * KSEL)

#define BM  128
#define BN  64
#define BK  64          // K per smem stage
#define LDA 72          // smem row stride (bf16 elems), padded

// ---------------- scratch ----------------
__device__ float d_act[(size_t)NPAIR * IDIM];   // fp32 activations
__device__ float d_y[(size_t)NPAIR * H];
__device__ int   d_pair_token[NPAIR];
__device__ float d_pair_weight[NPAIR];
__device__ int   d_token_pair[NTOK * 4];
__device__ int   d_cnt[NE];
__device__ int   d_fill[NE];
__device__ int   d_off[NEXP + 1];
__device__ int   d_tok_e[NTOK * KSEL];
__device__ float d_tok_w[NTOK * KSEL];

// split float4 -> 4 hi bf16 (uint2) + 4 lo bf16 (uint2)
__device__ __forceinline__ void split4(float4 v, uint2& hi, uint2& lo) {
    float f[4] = {v.x, v.y, v.z, v.w};
    uint32_t h[4], l[4];
#pragma unroll
    for (int i = 0; i < 4; i++) {
        __nv_bfloat16 hb = __float2bfloat16(f[i]);
        __nv_bfloat16 lb = __float2bfloat16(f[i] - __bfloat162float(hb));
        h[i] = (uint32_t)__bfloat16_as_ushort(hb);
        l[i] = (uint32_t)__bfloat16_as_ushort(lb);
    }
    hi = make_uint2(h[0] | (h[1] << 16), h[2] | (h[3] << 16));
    lo = make_uint2(l[0] | (l[1] << 16), l[2] | (l[3] << 16));
}

// ---------------- routing ----------------
__global__ void init_kernel() {
    int t = threadIdx.x;
    if (t < NE) { d_cnt[t] = 0; d_fill[t] = 0; }
}

__global__ __launch_bounds__(256) void router_kernel(const float* __restrict__ x,
                                                     const float* __restrict__ gw) {
    int warp = (blockIdx.x * blockDim.x + threadIdx.x) >> 5;
    int lane = threadIdx.x & 31;
    if (warp >= NTOK) return;
    const float* xr = x + (size_t)warp * H;
    float acc[NE];
#pragma unroll
    for (int e = 0; e < NE; e++) acc[e] = 0.f;
    for (int h = lane; h < H; h += 32) {
        float xv = xr[h];
#pragma unroll
        for (int e = 0; e < NE; e++) acc[e] += xv * gw[e * H + h];
    }
#pragma unroll
    for (int e = 0; e < NE; e++) {
#pragma unroll
        for (int o = 16; o > 0; o >>= 1) acc[e] += __shfl_xor_sync(0xFFFFFFFFu, acc[e], o);
    }
    if (lane == 0) {
        float mx = acc[0];
#pragma unroll
        for (int e = 1; e < NE; e++) mx = fmaxf(mx, acc[e]);
        float p[NE]; float s = 0.f;
#pragma unroll
        for (int e = 0; e < NE; e++) { p[e] = expf(acc[e] - mx); s += p[e]; }
        float inv = 1.f / s;
#pragma unroll
        for (int e = 0; e < NE; e++) p[e] *= inv;
        int e0 = 0; float w0 = p[0];
        int e1 = -1; float w1 = -1.f;
#pragma unroll
        for (int e = 1; e < NE; e++) {
            if (p[e] > w0) { e1 = e0; w1 = w0; e0 = e; w0 = p[e]; }
            else if (p[e] > w1) { e1 = e; w1 = p[e]; }
        }
        float denom = w0 + w1 + 1e-8f;
        d_tok_e[warp * 2 + 0] = e0;  d_tok_w[warp * 2 + 0] = w0 / denom;
        d_tok_e[warp * 2 + 1] = e1;  d_tok_w[warp * 2 + 1] = w1 / denom;
        atomicAdd(&d_cnt[e0], 1);
        atomicAdd(&d_cnt[e1], 1);
    }
}

__global__ void scan_kernel() {
    if (threadIdx.x == 0) {
        int acc = 0;
        for (int e = 0; e < NE; e++) { d_off[e] = acc; acc += d_cnt[e]; }
        d_off[NE]     = ROUTED_PAIRS;
        d_off[NE + 1] = ROUTED_PAIRS + NTOK;
        d_off[NE + 2] = ROUTED_PAIRS + 2 * NTOK;
    }
}

__global__ void build_pairs_kernel() {
    int t = blockIdx.x * blockDim.x + threadIdx.x;
    if (t >= NTOK) return;
#pragma unroll
    for (int k = 0; k < KSEL; k++) {
        int e = d_tok_e[t * 2 + k];
        float w = d_tok_w[t * 2 + k];
        int pos = d_off[e] + atomicAdd(&d_fill[e], 1);
        d_pair_token[pos] = t;
        d_pair_weight[pos] = w;
        d_token_pair[t * 4 + k] = pos;
    }
#pragma unroll
    for (int s = 0; s < NS; s++) {
        int pos = ROUTED_PAIRS + s * NTOK + t;
        d_pair_token[pos] = t;
        d_pair_weight[pos] = 0.5f;
        d_token_pair[t * 4 + 2 + s] = pos;
    }
}

// ---------------- up/gate GEMM: bf16x3 WMMA, fused SiLU ----------------
// smem: AsH 128x72 | AsL 128x72 | BgH 64x72 | BgL | BuH | BuL  (bf16)
#define UP_SMEM (2 * BM * LDA * 2 + 4 * BK * LDA * 2)   // 73728

__global__ __launch_bounds__(256) void up_kernel(const float* __restrict__ x,
                                                 const float* __restrict__ wg,
                                                 const float* __restrict__ wu,
                                                 const float* __restrict__ swg,
                                                 const float* __restrict__ swu) {
    int ez  = blockIdx.z;
    int off = d_off[ez];
    int cnt = d_off[ez + 1] - off;
    int m0  = blockIdx.y * BM;
    if (m0 >= cnt) return;
    int n0  = blockIdx.x * BN;

    const float* Bg = (ez < NE) ? wg + (size_t)ez * H * IDIM : swg + (size_t)(ez - NE) * H * IDIM;
    const float* Bu = (ez < NE) ? wu + (size_t)ez * H * IDIM : swu + (size_t)(ez - NE) * H * IDIM;

    extern __shared__ char smraw[];
    __nv_bfloat16* AsH = (__nv_bfloat16*)smraw;
    __nv_bfloat16* AsL = AsH + BM * LDA;
    __nv_bfloat16* BgH = AsL + BM * LDA;
    __nv_bfloat16* BgL = BgH + BK * LDA;
    __nv_bfloat16* BuH = BgL + BK * LDA;
    __nv_bfloat16* BuL = BuH + BK * LDA;
    float* ep = (float*)smraw;           // epilogue reuse: 128x64 fp32

    __shared__ int toks[BM];

    int tid = threadIdx.x, wid = tid >> 5;
    if (tid < BM) toks[tid] = d_pair_token[off + min(m0 + tid, cnt - 1)];
    __syncthreads();

    int mbase = (wid & 3) * 32;
    int nbase = (wid >> 2) * 32;

    wmma::fragment<wmma::accumulator, 16, 16, 16, float> accg[2][2], accu[2][2];
#pragma unroll
    for (int i = 0; i < 2; i++)
#pragma unroll
        for (int j = 0; j < 2; j++) { wmma::fill_fragment(accg[i][j], 0.f); wmma::fill_fragment(accu[i][j], 0.f); }

    for (int kt = 0; kt < H / BK; kt++) {
        int k0 = kt * BK;
        // A: 128 rows x 16 float4
#pragma unroll
        for (int idx = tid; idx < 2048; idx += 256) {
            int row = idx >> 4, c4 = idx & 15;
            float4 v = *(const float4*)(x + (size_t)toks[row] * H + k0 + c4 * 4);
            uint2 hi, lo; split4(v, hi, lo);
            *(uint2*)&AsH[row * LDA + c4 * 4] = hi;
            *(uint2*)&AsL[row * LDA + c4 * 4] = lo;
        }
        // B: 2 matrices x 64 rows x 16 float4
#pragma unroll
        for (int idx = tid; idx < 2048; idx += 256) {
            int mat = idx >> 10, r = (idx >> 4) & 63, c4 = idx & 15;
            const float* src = mat ? Bu : Bg;
            float4 v = __ldg((const float4*)(src + (size_t)(k0 + r) * IDIM + n0 + c4 * 4));
            uint2 hi, lo; split4(v, hi, lo);
            __nv_bfloat16* dh = mat ? BuH : BgH;
            __nv_bfloat16* dl = mat ? BuL : BgL;
            *(uint2*)&dh[r * LDA + c4 * 4] = hi;
            *(uint2*)&dl[r * LDA + c4 * 4] = lo;
        }
        __syncthreads();

#pragma unroll
        for (int ks = 0; ks < BK / 16; ks++) {
            int kc = ks * 16;
            wmma::fragment<wmma::matrix_a, 16, 16, 16, __nv_bfloat16, wmma::row_major> aH[2], aL[2];
#pragma unroll
            for (int i = 0; i < 2; i++) {
                wmma::load_matrix_sync(aH[i], &AsH[(mbase + i * 16) * LDA + kc], LDA);
                wmma::load_matrix_sync(aL[i], &AsL[(mbase + i * 16) * LDA + kc], LDA);
            }
#pragma unroll
            for (int j = 0; j < 2; j++) {
                wmma::fragment<wmma::matrix_b, 16, 16, 16, __nv_bfloat16, wmma::row_major> bgH, bgL, buH, buL;
                wmma::load_matrix_sync(bgH, &BgH[kc * LDA + nbase + j * 16], LDA);
                wmma::load_matrix_sync(bgL, &BgL[kc * LDA + nbase + j * 16], LDA);
                wmma::load_matrix_sync(buH, &BuH[kc * LDA + nbase + j * 16], LDA);
                wmma::load_matrix_sync(buL, &BuL[kc * LDA + nbase + j * 16], LDA);
#pragma unroll
                for (int i = 0; i < 2; i++) {
                    wmma::mma_sync(accg[i][j], aH[i], bgH, accg[i][j]);
                    wmma::mma_sync(accg[i][j], aH[i], bgL, accg[i][j]);
                    wmma::mma_sync(accg[i][j], aL[i], bgH, accg[i][j]);
                    wmma::mma_sync(accu[i][j], aH[i], buH, accu[i][j]);
                    wmma::mma_sync(accu[i][j], aH[i], buL, accu[i][j]);
                    wmma::mma_sync(accu[i][j], aL[i], buH, accu[i][j]);
                }
            }
        }
        __syncthreads();
    }

    // epilogue: act = silu(g)*u in registers, stage via smem, guarded write
#pragma unroll
    for (int i = 0; i < 2; i++)
#pragma unroll
        for (int j = 0; j < 2; j++) {
#pragma unroll
            for (int e = 0; e < accg[i][j].num_elements; e++) {
                float g = accg[i][j].x[e];
                float u = accu[i][j].x[e];
                accg[i][j].x[e] = (g / (1.f + expf(-g))) * u;
            }
            wmma::store_matrix_sync(&ep[(mbase + i * 16) * BN + nbase + j * 16], accg[i][j], BN, wmma::mem_row_major);
        }
    __syncthreads();
#pragma unroll
    for (int idx = tid; idx < 2048; idx += 256) {
        int row = idx >> 4, c4 = idx & 15;
        if (m0 + row < cnt)
            *(float4*)(d_act + (size_t)(off + m0 + row) * IDIM + n0 + c4 * 4) = *(float4*)&ep[row * BN + c4 * 4];
    }
}

// ---------------- down GEMM: bf16x3 WMMA ----------------
// smem: AsH 128x72 | AsL 128x72 | BH 64x72 | BL 64x72
#define DN_SMEM (2 * BM * LDA * 2 + 2 * BK * LDA * 2)   // 55296

__global__ __launch_bounds__(256) void down_kernel(const float* __restrict__ wd,
                                                   const float* __restrict__ swd) {
    int ez  = blockIdx.z;
    int off = d_off[ez];
    int cnt = d_off[ez + 1] - off;
    int m0  = blockIdx.y * BM;
    if (m0 >= cnt) return;
    int n0  = blockIdx.x * BN;

    const float* B = (ez < NE) ? wd + (size_t)ez * IDIM * H : swd + (size_t)(ez - NE) * IDIM * H;

    extern __shared__ char smraw[];
    __nv_bfloat16* AsH = (__nv_bfloat16*)smraw;
    __nv_bfloat16* AsL = AsH + BM * LDA;
    __nv_bfloat16* BH  = AsL + BM * LDA;
    __nv_bfloat16* BL  = BH + BK * LDA;
    float* ep = (float*)smraw;

    int tid = threadIdx.x, wid = tid >> 5;
    int mbase = (wid & 3) * 32;
    int nbase = (wid >> 2) * 32;

    wmma::fragment<wmma::accumulator, 16, 16, 16, float> acc[2][2];
#pragma unroll
    for (int i = 0; i < 2; i++)
#pragma unroll
        for (int j = 0; j < 2; j++) wmma::fill_fragment(acc[i][j], 0.f);

    for (int kt = 0; kt < IDIM / BK; kt++) {
        int k0 = kt * BK;
#pragma unroll
        for (int idx = tid; idx < 2048; idx += 256) {
            int row = idx >> 4, c4 = idx & 15;
            int pr = off + min(m0 + row, cnt - 1);
            float4 v = *(const float4*)(d_act + (size_t)pr * IDIM + k0 + c4 * 4);
            uint2 hi, lo; split4(v, hi, lo);
            *(uint2*)&AsH[row * LDA + c4 * 4] = hi;
            *(uint2*)&AsL[row * LDA + c4 * 4] = lo;
        }
#pragma unroll
        for (int idx = tid; idx < 1024; idx += 256) {
            int r = idx >> 4, c4 = idx & 15;
            float4 v = __ldg((const float4*)(B + (size_t)(k0 + r) * H + n0 + c4 * 4));
            uint2 hi, lo; split4(v, hi, lo);
            *(uint2*)&BH[r * LDA + c4 * 4] = hi;
            *(uint2*)&BL[r * LDA + c4 * 4] = lo;
        }
        __syncthreads();

#pragma unroll
        for (int ks = 0; ks < BK / 16; ks++) {
            int kc = ks * 16;
            wmma::fragment<wmma::matrix_a, 16, 16, 16, __nv_bfloat16, wmma::row_major> aH[2], aL[2];
#pragma unroll
            for (int i = 0; i < 2; i++) {
                wmma::load_matrix_sync(aH[i], &AsH[(mbase + i * 16) * LDA + kc], LDA);
                wmma::load_matrix_sync(aL[i], &AsL[(mbase + i * 16) * LDA + kc], LDA);
            }
#pragma unroll
            for (int j = 0; j < 2; j++) {
                wmma::fragment<wmma::matrix_b, 16, 16, 16, __nv_bfloat16, wmma::row_major> bH, bL;
                wmma::load_matrix_sync(bH, &BH[kc * LDA + nbase + j * 16], LDA);
                wmma::load_matrix_sync(bL, &BL[kc * LDA + nbase + j * 16], LDA);
#pragma unroll
                for (int i = 0; i < 2; i++) {
                    wmma::mma_sync(acc[i][j], aH[i], bH, acc[i][j]);
                    wmma::mma_sync(acc[i][j], aH[i], bL, acc[i][j]);
                    wmma::mma_sync(acc[i][j], aL[i], bH, acc[i][j]);
                }
            }
        }
        __syncthreads();
    }

#pragma unroll
    for (int i = 0; i < 2; i++)
#pragma unroll
        for (int j = 0; j < 2; j++)
            wmma::store_matrix_sync(&ep[(mbase + i * 16) * BN + nbase + j * 16], acc[i][j], BN, wmma::mem_row_major);
    __syncthreads();
#pragma unroll
    for (int idx = tid; idx < 2048; idx += 256) {
        int row = idx >> 4, c4 = idx & 15;
        if (m0 + row < cnt)
            *(float4*)(d_y + (size_t)(off + m0 + row) * H + n0 + c4 * 4) = *(float4*)&ep[row * BN + c4 * 4];
    }
}

// ---------------- combine ----------------
__global__ __launch_bounds__(256) void combine_kernel(float* __restrict__ out) {
    int t = blockIdx.x;
    int p0 = d_token_pair[t * 4 + 0], p1 = d_token_pair[t * 4 + 1];
    int p2 = d_token_pair[t * 4 + 2], p3 = d_token_pair[t * 4 + 3];
    float w0 = d_pair_weight[p0], w1 = d_pair_weight[p1];
    float w2 = d_pair_weight[p2], w3 = d_pair_weight[p3];
    const float* y0 = d_y + (size_t)p0 * H;
    const float* y1 = d_y + (size_t)p1 * H;
    const float* y2 = d_y + (size_t)p2 * H;
    const float* y3 = d_y + (size_t)p3 * H;
    float* o = out + (size_t)t * H;
    for (int h = threadIdx.x; h < H; h += blockDim.x)
        o[h] = w0 * y0[h] + w1 * y1[h] + w2 * y2[h] + w3 * y3[h];
}

// ---------------- launch ----------------
extern "C" void kernel_launch(void* const* d_in, const int* in_sizes, int n_in,
                              void* d_out, int out_size) {
    const float* x      = (const float*)d_in[0];
    const float* gate_w = (const float*)d_in[1];
    const float* swg    = (const float*)d_in[2];
    const float* swu    = (const float*)d_in[3];
    const float* swd    = (const float*)d_in[4];
    const float* wg     = (const float*)d_in[5];
    const float* wu     = (const float*)d_in[6];
    const float* wd     = (const float*)d_in[7];
    float* out = (float*)d_out;

    cudaFuncSetAttribute(up_kernel,   cudaFuncAttributeMaxDynamicSharedMemorySize, UP_SMEM);
    cudaFuncSetAttribute(down_kernel, cudaFuncAttributeMaxDynamicSharedMemorySize, DN_SMEM);

    init_kernel<<<1, 32>>>();
    router_kernel<<<NTOK / 8, 256>>>(x, gate_w);
    scan_kernel<<<1, 32>>>();
    build_pairs_kernel<<<NTOK / 256, 256>>>();

    dim3 gUp(IDIM / BN, NTOK / BM, NEXP);     // (48, 16, 18)
    up_kernel<<<gUp, 256, UP_SMEM>>>(x, wg, wu, swg, swu);

    dim3 gDown(H / BN, NTOK / BM, NEXP);      // (12, 16, 18)
    down_kernel<<<gDown, 256, DN_SMEM>>>(wd, swd);

    combine_kernel<<<NTOK, 256>>>(out);
}

// round 5
// speedup vs baseline: 1.7402x; 1.3294x over previous
#include <cuda_runtime.h>
#include <cuda_bf16.h>
#include <mma.h>
#include <math.h>
#include <stdint.h>

using namespace nvcuda;

#define H     768
#define IDIM  3072
#define NE    16
#define NS    2
#define NEXP  (NE + NS)
#define NTOK  2048
#define KSEL  2
#define NPAIR (NTOK * 4)
#define ROUTED_PAIRS (NTOK * KSEL)

#define BM  128
#define BN  64
#define BK  32            // K per pipeline stage
#define LDK 40            // A smem row stride (bf16)
#define LDB 72            // B smem row stride (bf16)

// ---------------- persistent scratch ----------------
__device__ __nv_bfloat16 d_wg_hi[(size_t)NE * H * IDIM];
__device__ __nv_bfloat16 d_wg_lo[(size_t)NE * H * IDIM];
__device__ __nv_bfloat16 d_wu_hi[(size_t)NE * H * IDIM];
__device__ __nv_bfloat16 d_wu_lo[(size_t)NE * H * IDIM];
__device__ __nv_bfloat16 d_wd_hi[(size_t)NE * IDIM * H];
__device__ __nv_bfloat16 d_wd_lo[(size_t)NE * IDIM * H];
__device__ __nv_bfloat16 d_sg_hi[(size_t)NS * H * IDIM];
__device__ __nv_bfloat16 d_sg_lo[(size_t)NS * H * IDIM];
__device__ __nv_bfloat16 d_su_hi[(size_t)NS * H * IDIM];
__device__ __nv_bfloat16 d_su_lo[(size_t)NS * H * IDIM];
__device__ __nv_bfloat16 d_sd_hi[(size_t)NS * IDIM * H];
__device__ __nv_bfloat16 d_sd_lo[(size_t)NS * IDIM * H];
__device__ __nv_bfloat16 d_xg_hi[(size_t)NPAIR * H];
__device__ __nv_bfloat16 d_xg_lo[(size_t)NPAIR * H];
__device__ __nv_bfloat16 d_act_hi[(size_t)NPAIR * IDIM];
__device__ __nv_bfloat16 d_act_lo[(size_t)NPAIR * IDIM];
__device__ float d_y[(size_t)NPAIR * H];
__device__ int   d_pair_token[NPAIR];
__device__ float d_pair_weight[NPAIR];
__device__ int   d_token_pair[NTOK * 4];
__device__ int   d_cnt[NE];
__device__ int   d_fill[NE];
__device__ int   d_off[NEXP + 1];
__device__ int   d_tok_e[NTOK * KSEL];
__device__ float d_tok_w[NTOK * KSEL];

// ---------------- helpers ----------------
__device__ __forceinline__ void split4(float4 v, uint2& hi, uint2& lo) {
    float f[4] = {v.x, v.y, v.z, v.w};
    uint32_t h[4], l[4];
#pragma unroll
    for (int i = 0; i < 4; i++) {
        __nv_bfloat16 hb = __float2bfloat16(f[i]);
        __nv_bfloat16 lb = __float2bfloat16(f[i] - __bfloat162float(hb));
        h[i] = (uint32_t)__bfloat16_as_ushort(hb);
        l[i] = (uint32_t)__bfloat16_as_ushort(lb);
    }
    hi = make_uint2(h[0] | (h[1] << 16), h[2] | (h[3] << 16));
    lo = make_uint2(l[0] | (l[1] << 16), l[2] | (l[3] << 16));
}

__device__ __forceinline__ uint32_t smem_u32(const void* p) {
    uint32_t a;
    asm("{ .reg .u64 t; cvta.to.shared.u64 t, %1; cvt.u32.u64 %0, t; }" : "=r"(a) : "l"(p));
    return a;
}
__device__ __forceinline__ void cp16(uint32_t d, const void* s) {
    asm volatile("cp.async.cg.shared.global [%0], [%1], 16;" :: "r"(d), "l"(s) : "memory");
}
#define CP_COMMIT() asm volatile("cp.async.commit_group;" ::: "memory")
template<int N> __device__ __forceinline__ void cp_wait() {
    asm volatile("cp.async.wait_group %0;" :: "n"(N) : "memory");
}

// ---------------- routing ----------------
__global__ void init_kernel() {
    int t = threadIdx.x;
    if (t < NE) { d_cnt[t] = 0; d_fill[t] = 0; }
}

__global__ __launch_bounds__(256) void router_kernel(const float* __restrict__ x,
                                                     const float* __restrict__ gw) {
    int warp = (blockIdx.x * blockDim.x + threadIdx.x) >> 5;
    int lane = threadIdx.x & 31;
    if (warp >= NTOK) return;
    const float* xr = x + (size_t)warp * H;
    float acc[NE];
#pragma unroll
    for (int e = 0; e < NE; e++) acc[e] = 0.f;
    for (int h = lane; h < H; h += 32) {
        float xv = xr[h];
#pragma unroll
        for (int e = 0; e < NE; e++) acc[e] += xv * gw[e * H + h];
    }
#pragma unroll
    for (int e = 0; e < NE; e++) {
#pragma unroll
        for (int o = 16; o > 0; o >>= 1) acc[e] += __shfl_xor_sync(0xFFFFFFFFu, acc[e], o);
    }
    if (lane == 0) {
        float mx = acc[0];
#pragma unroll
        for (int e = 1; e < NE; e++) mx = fmaxf(mx, acc[e]);
        float p[NE]; float s = 0.f;
#pragma unroll
        for (int e = 0; e < NE; e++) { p[e] = expf(acc[e] - mx); s += p[e]; }
        float inv = 1.f / s;
#pragma unroll
        for (int e = 0; e < NE; e++) p[e] *= inv;
        int e0 = 0; float w0 = p[0];
        int e1 = -1; float w1 = -1.f;
#pragma unroll
        for (int e = 1; e < NE; e++) {
            if (p[e] > w0) { e1 = e0; w1 = w0; e0 = e; w0 = p[e]; }
            else if (p[e] > w1) { e1 = e; w1 = p[e]; }
        }
        float denom = w0 + w1 + 1e-8f;
        d_tok_e[warp * 2 + 0] = e0;  d_tok_w[warp * 2 + 0] = w0 / denom;
        d_tok_e[warp * 2 + 1] = e1;  d_tok_w[warp * 2 + 1] = w1 / denom;
        atomicAdd(&d_cnt[e0], 1);
        atomicAdd(&d_cnt[e1], 1);
    }
}

__global__ void scan_kernel() {
    if (threadIdx.x == 0) {
        int acc = 0;
        for (int e = 0; e < NE; e++) { d_off[e] = acc; acc += d_cnt[e]; }
        d_off[NE]     = ROUTED_PAIRS;
        d_off[NE + 1] = ROUTED_PAIRS + NTOK;
        d_off[NE + 2] = ROUTED_PAIRS + 2 * NTOK;
    }
}

__global__ void build_pairs_kernel() {
    int t = blockIdx.x * blockDim.x + threadIdx.x;
    if (t >= NTOK) return;
#pragma unroll
    for (int k = 0; k < KSEL; k++) {
        int e = d_tok_e[t * 2 + k];
        float w = d_tok_w[t * 2 + k];
        int pos = d_off[e] + atomicAdd(&d_fill[e], 1);
        d_pair_token[pos] = t;
        d_pair_weight[pos] = w;
        d_token_pair[t * 4 + k] = pos;
    }
#pragma unroll
    for (int s = 0; s < NS; s++) {
        int pos = ROUTED_PAIRS + s * NTOK + t;
        d_pair_token[pos] = t;
        d_pair_weight[pos] = 0.5f;
        d_token_pair[t * 4 + 2 + s] = pos;
    }
}

// ---------------- weight pre-split (device-side symbol dispatch!) ----------------
// NOTE: __device__ globals are resolved in DEVICE code; host code must never
// take their address (that was the R4 bug).
__global__ __launch_bounds__(256) void split_all_kernel(
    const float4* __restrict__ wg,  const float4* __restrict__ wu,  const float4* __restrict__ wd,
    const float4* __restrict__ swg, const float4* __restrict__ swu, const float4* __restrict__ swd) {
    const int NR  = NE * H * IDIM / 4;   // 9437184
    const int NSH = NS * H * IDIM / 4;   // 1179648
    const int total = 3 * NR + 3 * NSH;  // 31850496
    for (int i = blockIdx.x * blockDim.x + threadIdx.x; i < total;
         i += gridDim.x * blockDim.x) {
        const float4* src; uint2* hi; uint2* lo; int idx;
        if (i < NR)            { src = wg;  hi = (uint2*)d_wg_hi; lo = (uint2*)d_wg_lo; idx = i; }
        else if (i < 2 * NR)   { src = wu;  hi = (uint2*)d_wu_hi; lo = (uint2*)d_wu_lo; idx = i - NR; }
        else if (i < 3 * NR)   { src = wd;  hi = (uint2*)d_wd_hi; lo = (uint2*)d_wd_lo; idx = i - 2 * NR; }
        else if (i < 3 * NR + NSH)     { src = swg; hi = (uint2*)d_sg_hi; lo = (uint2*)d_sg_lo; idx = i - 3 * NR; }
        else if (i < 3 * NR + 2 * NSH) { src = swu; hi = (uint2*)d_su_hi; lo = (uint2*)d_su_lo; idx = i - 3 * NR - NSH; }
        else                           { src = swd; hi = (uint2*)d_sd_hi; lo = (uint2*)d_sd_lo; idx = i - 3 * NR - 2 * NSH; }
        uint2 h, l;
        split4(__ldg(src + idx), h, l);
        hi[idx] = h;
        lo[idx] = l;
    }
}

// ---------------- gather + split token rows ----------------
__global__ __launch_bounds__(192) void gather_split_kernel(const float* __restrict__ x) {
    int p = blockIdx.x;
    int t = threadIdx.x;
    int tok = d_pair_token[p];
    float4 v = *(const float4*)(x + (size_t)tok * H + t * 4);
    uint2 hi, lo;
    split4(v, hi, lo);
    *(uint2*)(d_xg_hi + (size_t)p * H + t * 4) = hi;
    *(uint2*)(d_xg_lo + (size_t)p * H + t * 4) = lo;
}

// ---------------- up/gate GEMM: bf16x3 WMMA, cp.async double-buffered ----------------
#define ST_A   (BM * LDK * 2)            // 10240
#define ST_BUP (BK * LDB * 2)            // 4608
#define ST_UP  (2 * ST_A + 4 * ST_BUP)   // 38912
#define UP_SMEM (2 * ST_UP)              // 77824

__global__ __launch_bounds__(256) void up_kernel() {
    int ez  = blockIdx.z;
    int off = d_off[ez];
    int cnt = d_off[ez + 1] - off;
    int m0  = blockIdx.y * BM;
    if (m0 >= cnt) return;
    int n0  = blockIdx.x * BN;

    const __nv_bfloat16* BgH;
    const __nv_bfloat16* BgL;
    const __nv_bfloat16* BuH;
    const __nv_bfloat16* BuL;
    if (ez < NE) {
        size_t wo = (size_t)ez * H * IDIM;
        BgH = d_wg_hi + wo; BgL = d_wg_lo + wo; BuH = d_wu_hi + wo; BuL = d_wu_lo + wo;
    } else {
        size_t wo = (size_t)(ez - NE) * H * IDIM;
        BgH = d_sg_hi + wo; BgL = d_sg_lo + wo; BuH = d_su_hi + wo; BuL = d_su_lo + wo;
    }

    extern __shared__ char smraw[];
    uint32_t sb = smem_u32(smraw);
    float* ep = (float*)smraw;

    int tid = threadIdx.x, wid = tid >> 5;
    int mbase = (wid & 3) * 32;
    int nbase = (wid >> 2) * 32;

    wmma::fragment<wmma::accumulator, 16, 16, 16, float> accg[2][2], accu[2][2];
#pragma unroll
    for (int i = 0; i < 2; i++)
#pragma unroll
        for (int j = 0; j < 2; j++) { wmma::fill_fragment(accg[i][j], 0.f); wmma::fill_fragment(accu[i][j], 0.f); }

    auto load_stage = [&](int s, int k0) {
        uint32_t st = sb + s * ST_UP;
#pragma unroll
        for (int c = tid; c < 2048; c += 256) {
            if (c < 1024) {
                int split = c >> 9, row = (c >> 2) & 127, q = c & 3;
                int pr = off + min(m0 + row, cnt - 1);
                const __nv_bfloat16* src = (split ? d_xg_lo : d_xg_hi) + (size_t)pr * H + k0 + q * 8;
                cp16(st + split * ST_A + row * (LDK * 2) + q * 16, src);
            } else {
                int b = c - 1024;
                int mat = b >> 8, r = (b >> 3) & 31, q = b & 7;
                const __nv_bfloat16* base = (mat == 0) ? BgH : (mat == 1) ? BgL : (mat == 2) ? BuH : BuL;
                const __nv_bfloat16* src = base + (size_t)(k0 + r) * IDIM + n0 + q * 8;
                cp16(st + 2 * ST_A + mat * ST_BUP + r * (LDB * 2) + q * 16, src);
            }
        }
    };

    const int KT = H / BK;   // 24
    load_stage(0, 0);
    CP_COMMIT();

    for (int kt = 0; kt < KT; kt++) {
        if (kt + 1 < KT) { load_stage((kt + 1) & 1, (kt + 1) * BK); CP_COMMIT(); cp_wait<1>(); }
        else cp_wait<0>();
        __syncthreads();

        char* st = smraw + (kt & 1) * ST_UP;
        __nv_bfloat16* AH = (__nv_bfloat16*)st;
        __nv_bfloat16* AL = (__nv_bfloat16*)(st + ST_A);
        __nv_bfloat16* GH = (__nv_bfloat16*)(st + 2 * ST_A);
        __nv_bfloat16* GL = (__nv_bfloat16*)(st + 2 * ST_A + ST_BUP);
        __nv_bfloat16* UH = (__nv_bfloat16*)(st + 2 * ST_A + 2 * ST_BUP);
        __nv_bfloat16* UL = (__nv_bfloat16*)(st + 2 * ST_A + 3 * ST_BUP);

#pragma unroll
        for (int ks = 0; ks < BK / 16; ks++) {
            int kc = ks * 16;
            wmma::fragment<wmma::matrix_a, 16, 16, 16, __nv_bfloat16, wmma::row_major> aH[2], aL[2];
#pragma unroll
            for (int i = 0; i < 2; i++) {
                wmma::load_matrix_sync(aH[i], &AH[(mbase + i * 16) * LDK + kc], LDK);
                wmma::load_matrix_sync(aL[i], &AL[(mbase + i * 16) * LDK + kc], LDK);
            }
#pragma unroll
            for (int j = 0; j < 2; j++) {
                wmma::fragment<wmma::matrix_b, 16, 16, 16, __nv_bfloat16, wmma::row_major> bgH, bgL, buH, buL;
                wmma::load_matrix_sync(bgH, &GH[kc * LDB + nbase + j * 16], LDB);
                wmma::load_matrix_sync(bgL, &GL[kc * LDB + nbase + j * 16], LDB);
                wmma::load_matrix_sync(buH, &UH[kc * LDB + nbase + j * 16], LDB);
                wmma::load_matrix_sync(buL, &UL[kc * LDB + nbase + j * 16], LDB);
#pragma unroll
                for (int i = 0; i < 2; i++) {
                    wmma::mma_sync(accg[i][j], aH[i], bgH, accg[i][j]);
                    wmma::mma_sync(accg[i][j], aH[i], bgL, accg[i][j]);
                    wmma::mma_sync(accg[i][j], aL[i], bgH, accg[i][j]);
                    wmma::mma_sync(accu[i][j], aH[i], buH, accu[i][j]);
                    wmma::mma_sync(accu[i][j], aH[i], buL, accu[i][j]);
                    wmma::mma_sync(accu[i][j], aL[i], buH, accu[i][j]);
                }
            }
        }
        __syncthreads();
    }

    // epilogue: silu(g)*u -> split bf16 hi/lo
#pragma unroll
    for (int i = 0; i < 2; i++)
#pragma unroll
        for (int j = 0; j < 2; j++) {
#pragma unroll
            for (int e = 0; e < accg[i][j].num_elements; e++) {
                float g = accg[i][j].x[e];
                float u = accu[i][j].x[e];
                accg[i][j].x[e] = (g / (1.f + expf(-g))) * u;
            }
            wmma::store_matrix_sync(&ep[(mbase + i * 16) * BN + nbase + j * 16], accg[i][j], BN, wmma::mem_row_major);
        }
    __syncthreads();
#pragma unroll
    for (int idx = tid; idx < 2048; idx += 256) {
        int row = idx >> 4, c4 = idx & 15;
        if (m0 + row < cnt) {
            float4 v = *(float4*)&ep[row * BN + c4 * 4];
            uint2 hi, lo; split4(v, hi, lo);
            size_t o = (size_t)(off + m0 + row) * IDIM + n0 + c4 * 4;
            *(uint2*)(d_act_hi + o) = hi;
            *(uint2*)(d_act_lo + o) = lo;
        }
    }
}

// ---------------- down GEMM ----------------
#define ST_DN (2 * ST_A + 2 * ST_BUP)   // 29696
#define DN_SMEM (2 * ST_DN)             // 59392

__global__ __launch_bounds__(256) void down_kernel() {
    int ez  = blockIdx.z;
    int off = d_off[ez];
    int cnt = d_off[ez + 1] - off;
    int m0  = blockIdx.y * BM;
    if (m0 >= cnt) return;
    int n0  = blockIdx.x * BN;

    const __nv_bfloat16* BH_g;
    const __nv_bfloat16* BL_g;
    if (ez < NE) {
        size_t wo = (size_t)ez * IDIM * H;
        BH_g = d_wd_hi + wo; BL_g = d_wd_lo + wo;
    } else {
        size_t wo = (size_t)(ez - NE) * IDIM * H;
        BH_g = d_sd_hi + wo; BL_g = d_sd_lo + wo;
    }

    extern __shared__ char smraw[];
    uint32_t sb = smem_u32(smraw);
    float* ep = (float*)smraw;

    int tid = threadIdx.x, wid = tid >> 5;
    int mbase = (wid & 3) * 32;
    int nbase = (wid >> 2) * 32;

    wmma::fragment<wmma::accumulator, 16, 16, 16, float> acc[2][2];
#pragma unroll
    for (int i = 0; i < 2; i++)
#pragma unroll
        for (int j = 0; j < 2; j++) wmma::fill_fragment(acc[i][j], 0.f);

    auto load_stage = [&](int s, int k0) {
        uint32_t st = sb + s * ST_DN;
#pragma unroll
        for (int c = tid; c < 1536; c += 256) {
            if (c < 1024) {
                int split = c >> 9, row = (c >> 2) & 127, q = c & 3;
                int pr = off + min(m0 + row, cnt - 1);
                const __nv_bfloat16* src = (split ? d_act_lo : d_act_hi) + (size_t)pr * IDIM + k0 + q * 8;
                cp16(st + split * ST_A + row * (LDK * 2) + q * 16, src);
            } else {
                int b = c - 1024;
                int mat = b >> 8, r = (b >> 3) & 31, q = b & 7;
                const __nv_bfloat16* src = (mat ? BL_g : BH_g) + (size_t)(k0 + r) * H + n0 + q * 8;
                cp16(st + 2 * ST_A + mat * ST_BUP + r * (LDB * 2) + q * 16, src);
            }
        }
    };

    const int KT = IDIM / BK;   // 96
    load_stage(0, 0);
    CP_COMMIT();

    for (int kt = 0; kt < KT; kt++) {
        if (kt + 1 < KT) { load_stage((kt + 1) & 1, (kt + 1) * BK); CP_COMMIT(); cp_wait<1>(); }
        else cp_wait<0>();
        __syncthreads();

        char* st = smraw + (kt & 1) * ST_DN;
        __nv_bfloat16* AH = (__nv_bfloat16*)st;
        __nv_bfloat16* AL = (__nv_bfloat16*)(st + ST_A);
        __nv_bfloat16* BH = (__nv_bfloat16*)(st + 2 * ST_A);
        __nv_bfloat16* BL = (__nv_bfloat16*)(st + 2 * ST_A + ST_BUP);

#pragma unroll
        for (int ks = 0; ks < BK / 16; ks++) {
            int kc = ks * 16;
            wmma::fragment<wmma::matrix_a, 16, 16, 16, __nv_bfloat16, wmma::row_major> aH[2], aL[2];
#pragma unroll
            for (int i = 0; i < 2; i++) {
                wmma::load_matrix_sync(aH[i], &AH[(mbase + i * 16) * LDK + kc], LDK);
                wmma::load_matrix_sync(aL[i], &AL[(mbase + i * 16) * LDK + kc], LDK);
            }
#pragma unroll
            for (int j = 0; j < 2; j++) {
                wmma::fragment<wmma::matrix_b, 16, 16, 16, __nv_bfloat16, wmma::row_major> bH, bL;
                wmma::load_matrix_sync(bH, &BH[kc * LDB + nbase + j * 16], LDB);
                wmma::load_matrix_sync(bL, &BL[kc * LDB + nbase + j * 16], LDB);
#pragma unroll
                for (int i = 0; i < 2; i++) {
                    wmma::mma_sync(acc[i][j], aH[i], bH, acc[i][j]);
                    wmma::mma_sync(acc[i][j], aH[i], bL, acc[i][j]);
                    wmma::mma_sync(acc[i][j], aL[i], bH, acc[i][j]);
                }
            }
        }
        __syncthreads();
    }

#pragma unroll
    for (int i = 0; i < 2; i++)
#pragma unroll
        for (int j = 0; j < 2; j++)
            wmma::store_matrix_sync(&ep[(mbase + i * 16) * BN + nbase + j * 16], acc[i][j], BN, wmma::mem_row_major);
    __syncthreads();
#pragma unroll
    for (int idx = tid; idx < 2048; idx += 256) {
        int row = idx >> 4, c4 = idx & 15;
        if (m0 + row < cnt)
            *(float4*)(d_y + (size_t)(off + m0 + row) * H + n0 + c4 * 4) = *(float4*)&ep[row * BN + c4 * 4];
    }
}

// ---------------- combine ----------------
__global__ __launch_bounds__(256) void combine_kernel(float* __restrict__ out) {
    int t = blockIdx.x;
    int p0 = d_token_pair[t * 4 + 0], p1 = d_token_pair[t * 4 + 1];
    int p2 = d_token_pair[t * 4 + 2], p3 = d_token_pair[t * 4 + 3];
    float w0 = d_pair_weight[p0], w1 = d_pair_weight[p1];
    float w2 = d_pair_weight[p2], w3 = d_pair_weight[p3];
    const float* y0 = d_y + (size_t)p0 * H;
    const float* y1 = d_y + (size_t)p1 * H;
    const float* y2 = d_y + (size_t)p2 * H;
    const float* y3 = d_y + (size_t)p3 * H;
    float* o = out + (size_t)t * H;
    for (int h = threadIdx.x; h < H; h += blockDim.x)
        o[h] = w0 * y0[h] + w1 * y1[h] + w2 * y2[h] + w3 * y3[h];
}

// ---------------- launch ----------------
extern "C" void kernel_launch(void* const* d_in, const int* in_sizes, int n_in,
                              void* d_out, int out_size) {
    const float* x      = (const float*)d_in[0];
    const float* gate_w = (const float*)d_in[1];
    const float* swg    = (const float*)d_in[2];
    const float* swu    = (const float*)d_in[3];
    const float* swd    = (const float*)d_in[4];
    const float* wg     = (const float*)d_in[5];
    const float* wu     = (const float*)d_in[6];
    const float* wd     = (const float*)d_in[7];
    float* out = (float*)d_out;

    cudaFuncSetAttribute(up_kernel,   cudaFuncAttributeMaxDynamicSharedMemorySize, UP_SMEM);
    cudaFuncSetAttribute(down_kernel, cudaFuncAttributeMaxDynamicSharedMemorySize, DN_SMEM);

    // weight pre-split (destinations resolved in device code)
    split_all_kernel<<<4096, 256>>>((const float4*)wg, (const float4*)wu, (const float4*)wd,
                                    (const float4*)swg, (const float4*)swu, (const float4*)swd);

    init_kernel<<<1, 32>>>();
    router_kernel<<<NTOK / 8, 256>>>(x, gate_w);
    scan_kernel<<<1, 32>>>();
    build_pairs_kernel<<<NTOK / 256, 256>>>();
    gather_split_kernel<<<NPAIR, 192>>>(x);

    dim3 gUp(IDIM / BN, NTOK / BM, NEXP);     // (48, 16, 18)
    up_kernel<<<gUp, 256, UP_SMEM>>>();

    dim3 gDown(H / BN, NTOK / BM, NEXP);      // (12, 16, 18)
    down_kernel<<<gDown, 256, DN_SMEM>>>();

    combine_kernel<<<NTOK, 256>>>(out);
}

// round 6
// speedup vs baseline: 2.9972x; 1.7224x over previous
#include <cuda_runtime.h>
#include <cuda_fp16.h>
#include <mma.h>
#include <math.h>
#include <stdint.h>

using namespace nvcuda;

#define H     768
#define IDIM  3072
#define NE    16
#define NS    2
#define NEXP  (NE + NS)
#define NTOK  2048
#define KSEL  2
#define NPAIR (NTOK * 4)
#define ROUTED_PAIRS (NTOK * KSEL)

#define BM  128
#define BN  64
#define BK  32            // K per pipeline stage
#define LDK 40            // A smem row stride (fp16)
#define LDB 72            // B smem row stride (fp16)

// ---------------- persistent scratch ----------------
__device__ __half d_wg_h[(size_t)NE * H * IDIM];
__device__ __half d_wu_h[(size_t)NE * H * IDIM];
__device__ __half d_wd_h[(size_t)NE * IDIM * H];
__device__ __half d_sg_h[(size_t)NS * H * IDIM];
__device__ __half d_su_h[(size_t)NS * H * IDIM];
__device__ __half d_sd_h[(size_t)NS * IDIM * H];
__device__ __half d_xg_hi[(size_t)NPAIR * H];
__device__ __half d_xg_lo[(size_t)NPAIR * H];
__device__ __half d_act_hi[(size_t)NPAIR * IDIM];
__device__ __half d_act_lo[(size_t)NPAIR * IDIM];
__device__ float d_y[(size_t)NPAIR * H];
__device__ int   d_pair_token[NPAIR];
__device__ float d_pair_weight[NPAIR];
__device__ int   d_token_pair[NTOK * 4];
__device__ int   d_cnt[NE];
__device__ int   d_fill[NE];
__device__ int   d_off[NEXP + 1];
__device__ int   d_tok_e[NTOK * KSEL];
__device__ float d_tok_w[NTOK * KSEL];

// ---------------- helpers ----------------
// split float4 into fp16 hi (uint2) + fp16 lo (uint2)
__device__ __forceinline__ void splitH4(float4 v, uint2& hi, uint2& lo) {
    float f[4] = {v.x, v.y, v.z, v.w};
    uint32_t h[4], l[4];
#pragma unroll
    for (int i = 0; i < 4; i++) {
        __half hb = __float2half_rn(f[i]);
        __half lb = __float2half_rn(f[i] - __half2float(hb));
        h[i] = (uint32_t)__half_as_ushort(hb);
        l[i] = (uint32_t)__half_as_ushort(lb);
    }
    hi = make_uint2(h[0] | (h[1] << 16), h[2] | (h[3] << 16));
    lo = make_uint2(l[0] | (l[1] << 16), l[2] | (l[3] << 16));
}
// convert float4 -> 4 fp16 packed in uint2
__device__ __forceinline__ uint2 cvtH4(float4 v) {
    uint32_t a = (uint32_t)__half_as_ushort(__float2half_rn(v.x))
               | ((uint32_t)__half_as_ushort(__float2half_rn(v.y)) << 16);
    uint32_t b = (uint32_t)__half_as_ushort(__float2half_rn(v.z))
               | ((uint32_t)__half_as_ushort(__float2half_rn(v.w)) << 16);
    return make_uint2(a, b);
}

__device__ __forceinline__ uint32_t smem_u32(const void* p) {
    uint32_t a;
    asm("{ .reg .u64 t; cvta.to.shared.u64 t, %1; cvt.u32.u64 %0, t; }" : "=r"(a) : "l"(p));
    return a;
}
__device__ __forceinline__ void cp16(uint32_t d, const void* s) {
    asm volatile("cp.async.cg.shared.global [%0], [%1], 16;" :: "r"(d), "l"(s) : "memory");
}
#define CP_COMMIT() asm volatile("cp.async.commit_group;" ::: "memory")
template<int N> __device__ __forceinline__ void cp_wait() {
    asm volatile("cp.async.wait_group %0;" :: "n"(N) : "memory");
}

// ---------------- routing ----------------
__global__ void init_kernel() {
    int t = threadIdx.x;
    if (t < NE) { d_cnt[t] = 0; d_fill[t] = 0; }
}

__global__ __launch_bounds__(256) void router_kernel(const float* __restrict__ x,
                                                     const float* __restrict__ gw) {
    int warp = (blockIdx.x * blockDim.x + threadIdx.x) >> 5;
    int lane = threadIdx.x & 31;
    if (warp >= NTOK) return;
    const float* xr = x + (size_t)warp * H;
    float acc[NE];
#pragma unroll
    for (int e = 0; e < NE; e++) acc[e] = 0.f;
    for (int h = lane; h < H; h += 32) {
        float xv = xr[h];
#pragma unroll
        for (int e = 0; e < NE; e++) acc[e] += xv * gw[e * H + h];
    }
#pragma unroll
    for (int e = 0; e < NE; e++) {
#pragma unroll
        for (int o = 16; o > 0; o >>= 1) acc[e] += __shfl_xor_sync(0xFFFFFFFFu, acc[e], o);
    }
    if (lane == 0) {
        float mx = acc[0];
#pragma unroll
        for (int e = 1; e < NE; e++) mx = fmaxf(mx, acc[e]);
        float p[NE]; float s = 0.f;
#pragma unroll
        for (int e = 0; e < NE; e++) { p[e] = expf(acc[e] - mx); s += p[e]; }
        float inv = 1.f / s;
#pragma unroll
        for (int e = 0; e < NE; e++) p[e] *= inv;
        int e0 = 0; float w0 = p[0];
        int e1 = -1; float w1 = -1.f;
#pragma unroll
        for (int e = 1; e < NE; e++) {
            if (p[e] > w0) { e1 = e0; w1 = w0; e0 = e; w0 = p[e]; }
            else if (p[e] > w1) { e1 = e; w1 = p[e]; }
        }
        float denom = w0 + w1 + 1e-8f;
        d_tok_e[warp * 2 + 0] = e0;  d_tok_w[warp * 2 + 0] = w0 / denom;
        d_tok_e[warp * 2 + 1] = e1;  d_tok_w[warp * 2 + 1] = w1 / denom;
        atomicAdd(&d_cnt[e0], 1);
        atomicAdd(&d_cnt[e1], 1);
    }
}

__global__ void scan_kernel() {
    if (threadIdx.x == 0) {
        int acc = 0;
        for (int e = 0; e < NE; e++) { d_off[e] = acc; acc += d_cnt[e]; }
        d_off[NE]     = ROUTED_PAIRS;
        d_off[NE + 1] = ROUTED_PAIRS + NTOK;
        d_off[NE + 2] = ROUTED_PAIRS + 2 * NTOK;
    }
}

__global__ void build_pairs_kernel() {
    int t = blockIdx.x * blockDim.x + threadIdx.x;
    if (t >= NTOK) return;
#pragma unroll
    for (int k = 0; k < KSEL; k++) {
        int e = d_tok_e[t * 2 + k];
        float w = d_tok_w[t * 2 + k];
        int pos = d_off[e] + atomicAdd(&d_fill[e], 1);
        d_pair_token[pos] = t;
        d_pair_weight[pos] = w;
        d_token_pair[t * 4 + k] = pos;
    }
#pragma unroll
    for (int s = 0; s < NS; s++) {
        int pos = ROUTED_PAIRS + s * NTOK + t;
        d_pair_token[pos] = t;
        d_pair_weight[pos] = 0.5f;
        d_token_pair[t * 4 + 2 + s] = pos;
    }
}

// ---------------- weight conversion to fp16 (device-side symbol dispatch) ----------------
__global__ __launch_bounds__(256) void convert_all_kernel(
    const float4* __restrict__ wg,  const float4* __restrict__ wu,  const float4* __restrict__ wd,
    const float4* __restrict__ swg, const float4* __restrict__ swu, const float4* __restrict__ swd) {
    const int NR  = NE * H * IDIM / 4;   // 9437184
    const int NSH = NS * H * IDIM / 4;   // 1179648
    const int total = 3 * NR + 3 * NSH;
    for (int i = blockIdx.x * blockDim.x + threadIdx.x; i < total;
         i += gridDim.x * blockDim.x) {
        const float4* src; uint2* dst; int idx;
        if (i < NR)                    { src = wg;  dst = (uint2*)d_wg_h; idx = i; }
        else if (i < 2 * NR)           { src = wu;  dst = (uint2*)d_wu_h; idx = i - NR; }
        else if (i < 3 * NR)           { src = wd;  dst = (uint2*)d_wd_h; idx = i - 2 * NR; }
        else if (i < 3 * NR + NSH)     { src = swg; dst = (uint2*)d_sg_h; idx = i - 3 * NR; }
        else if (i < 3 * NR + 2 * NSH) { src = swu; dst = (uint2*)d_su_h; idx = i - 3 * NR - NSH; }
        else                           { src = swd; dst = (uint2*)d_sd_h; idx = i - 3 * NR - 2 * NSH; }
        dst[idx] = cvtH4(__ldg(src + idx));
    }
}

// ---------------- gather + fp16 split of token rows ----------------
__global__ __launch_bounds__(192) void gather_split_kernel(const float* __restrict__ x) {
    int p = blockIdx.x;
    int t = threadIdx.x;
    int tok = d_pair_token[p];
    float4 v = *(const float4*)(x + (size_t)tok * H + t * 4);
    uint2 hi, lo;
    splitH4(v, hi, lo);
    *(uint2*)(d_xg_hi + (size_t)p * H + t * 4) = hi;
    *(uint2*)(d_xg_lo + (size_t)p * H + t * 4) = lo;
}

// ---------------- up/gate GEMM: fp16 A-split x2, cp.async double-buffered ----------------
#define ST_A   (BM * LDK * 2)            // 10240
#define ST_B1  (BK * LDB * 2)            // 4608
#define ST_UP  (2 * ST_A + 2 * ST_B1)    // 29696
#define UP_SMEM (2 * ST_UP)              // 59392

__global__ __launch_bounds__(256) void up_kernel() {
    int ez  = blockIdx.z;
    int off = d_off[ez];
    int cnt = d_off[ez + 1] - off;
    int m0  = blockIdx.y * BM;
    if (m0 >= cnt) return;
    int n0  = blockIdx.x * BN;

    const __half* Bg;
    const __half* Bu;
    if (ez < NE) {
        size_t wo = (size_t)ez * H * IDIM;
        Bg = d_wg_h + wo; Bu = d_wu_h + wo;
    } else {
        size_t wo = (size_t)(ez - NE) * H * IDIM;
        Bg = d_sg_h + wo; Bu = d_su_h + wo;
    }

    extern __shared__ char smraw[];
    uint32_t sb = smem_u32(smraw);
    float* ep = (float*)smraw;

    int tid = threadIdx.x, wid = tid >> 5;
    int mbase = (wid & 3) * 32;
    int nbase = (wid >> 2) * 32;

    wmma::fragment<wmma::accumulator, 16, 16, 16, float> accg[2][2], accu[2][2];
#pragma unroll
    for (int i = 0; i < 2; i++)
#pragma unroll
        for (int j = 0; j < 2; j++) { wmma::fill_fragment(accg[i][j], 0.f); wmma::fill_fragment(accu[i][j], 0.f); }

    // 1536 16B chunks: A hi/lo 1024, Bg/Bu 512
    auto load_stage = [&](int s, int k0) {
        uint32_t st = sb + s * ST_UP;
#pragma unroll
        for (int c = tid; c < 1536; c += 256) {
            if (c < 1024) {
                int split = c >> 9, row = (c >> 2) & 127, q = c & 3;
                int pr = off + min(m0 + row, cnt - 1);
                const __half* src = (split ? d_xg_lo : d_xg_hi) + (size_t)pr * H + k0 + q * 8;
                cp16(st + split * ST_A + row * (LDK * 2) + q * 16, src);
            } else {
                int b = c - 1024;
                int mat = b >> 8, r = (b >> 3) & 31, q = b & 7;
                const __half* src = (mat ? Bu : Bg) + (size_t)(k0 + r) * IDIM + n0 + q * 8;
                cp16(st + 2 * ST_A + mat * ST_B1 + r * (LDB * 2) + q * 16, src);
            }
        }
    };

    const int KT = H / BK;   // 24
    load_stage(0, 0);
    CP_COMMIT();

    for (int kt = 0; kt < KT; kt++) {
        if (kt + 1 < KT) { load_stage((kt + 1) & 1, (kt + 1) * BK); CP_COMMIT(); cp_wait<1>(); }
        else cp_wait<0>();
        __syncthreads();

        char* st = smraw + (kt & 1) * ST_UP;
        __half* AH = (__half*)st;
        __half* AL = (__half*)(st + ST_A);
        __half* BGs = (__half*)(st + 2 * ST_A);
        __half* BUs = (__half*)(st + 2 * ST_A + ST_B1);

#pragma unroll
        for (int ks = 0; ks < BK / 16; ks++) {
            int kc = ks * 16;
            wmma::fragment<wmma::matrix_a, 16, 16, 16, __half, wmma::row_major> aH[2], aL[2];
#pragma unroll
            for (int i = 0; i < 2; i++) {
                wmma::load_matrix_sync(aH[i], &AH[(mbase + i * 16) * LDK + kc], LDK);
                wmma::load_matrix_sync(aL[i], &AL[(mbase + i * 16) * LDK + kc], LDK);
            }
#pragma unroll
            for (int j = 0; j < 2; j++) {
                wmma::fragment<wmma::matrix_b, 16, 16, 16, __half, wmma::row_major> bg, bu;
                wmma::load_matrix_sync(bg, &BGs[kc * LDB + nbase + j * 16], LDB);
                wmma::load_matrix_sync(bu, &BUs[kc * LDB + nbase + j * 16], LDB);
#pragma unroll
                for (int i = 0; i < 2; i++) {
                    wmma::mma_sync(accg[i][j], aH[i], bg, accg[i][j]);
                    wmma::mma_sync(accg[i][j], aL[i], bg, accg[i][j]);
                    wmma::mma_sync(accu[i][j], aH[i], bu, accu[i][j]);
                    wmma::mma_sync(accu[i][j], aL[i], bu, accu[i][j]);
                }
            }
        }
        __syncthreads();
    }

    // epilogue: silu(g)*u -> fp16 hi/lo split
#pragma unroll
    for (int i = 0; i < 2; i++)
#pragma unroll
        for (int j = 0; j < 2; j++) {
#pragma unroll
            for (int e = 0; e < accg[i][j].num_elements; e++) {
                float g = accg[i][j].x[e];
                float u = accu[i][j].x[e];
                accg[i][j].x[e] = (g / (1.f + expf(-g))) * u;
            }
            wmma::store_matrix_sync(&ep[(mbase + i * 16) * BN + nbase + j * 16], accg[i][j], BN, wmma::mem_row_major);
        }
    __syncthreads();
#pragma unroll
    for (int idx = tid; idx < 2048; idx += 256) {
        int row = idx >> 4, c4 = idx & 15;
        if (m0 + row < cnt) {
            float4 v = *(float4*)&ep[row * BN + c4 * 4];
            uint2 hi, lo; splitH4(v, hi, lo);
            size_t o = (size_t)(off + m0 + row) * IDIM + n0 + c4 * 4;
            *(uint2*)(d_act_hi + o) = hi;
            *(uint2*)(d_act_lo + o) = lo;
        }
    }
}

// ---------------- down GEMM: fp16 A-split x2 ----------------
#define ST_DN (2 * ST_A + ST_B1)        // 25088
#define DN_SMEM (2 * ST_DN)             // 50176

__global__ __launch_bounds__(256) void down_kernel() {
    int ez  = blockIdx.z;
    int off = d_off[ez];
    int cnt = d_off[ez + 1] - off;
    int m0  = blockIdx.y * BM;
    if (m0 >= cnt) return;
    int n0  = blockIdx.x * BN;

    const __half* Bw = (ez < NE) ? d_wd_h + (size_t)ez * IDIM * H
                                 : d_sd_h + (size_t)(ez - NE) * IDIM * H;

    extern __shared__ char smraw[];
    uint32_t sb = smem_u32(smraw);
    float* ep = (float*)smraw;

    int tid = threadIdx.x, wid = tid >> 5;
    int mbase = (wid & 3) * 32;
    int nbase = (wid >> 2) * 32;

    wmma::fragment<wmma::accumulator, 16, 16, 16, float> acc[2][2];
#pragma unroll
    for (int i = 0; i < 2; i++)
#pragma unroll
        for (int j = 0; j < 2; j++) wmma::fill_fragment(acc[i][j], 0.f);

    auto load_stage = [&](int s, int k0) {
        uint32_t st = sb + s * ST_DN;
#pragma unroll
        for (int c = tid; c < 1280; c += 256) {
            if (c < 1024) {
                int split = c >> 9, row = (c >> 2) & 127, q = c & 3;
                int pr = off + min(m0 + row, cnt - 1);
                const __half* src = (split ? d_act_lo : d_act_hi) + (size_t)pr * IDIM + k0 + q * 8;
                cp16(st + split * ST_A + row * (LDK * 2) + q * 16, src);
            } else {
                int b = c - 1024;
                int r = b >> 3, q = b & 7;
                const __half* src = Bw + (size_t)(k0 + r) * H + n0 + q * 8;
                cp16(st + 2 * ST_A + r * (LDB * 2) + q * 16, src);
            }
        }
    };

    const int KT = IDIM / BK;   // 96
    load_stage(0, 0);
    CP_COMMIT();

    for (int kt = 0; kt < KT; kt++) {
        if (kt + 1 < KT) { load_stage((kt + 1) & 1, (kt + 1) * BK); CP_COMMIT(); cp_wait<1>(); }
        else cp_wait<0>();
        __syncthreads();

        char* st = smraw + (kt & 1) * ST_DN;
        __half* AH = (__half*)st;
        __half* AL = (__half*)(st + ST_A);
        __half* Bs = (__half*)(st + 2 * ST_A);

#pragma unroll
        for (int ks = 0; ks < BK / 16; ks++) {
            int kc = ks * 16;
            wmma::fragment<wmma::matrix_a, 16, 16, 16, __half, wmma::row_major> aH[2], aL[2];
#pragma unroll
            for (int i = 0; i < 2; i++) {
                wmma::load_matrix_sync(aH[i], &AH[(mbase + i * 16) * LDK + kc], LDK);
                wmma::load_matrix_sync(aL[i], &AL[(mbase + i * 16) * LDK + kc], LDK);
            }
#pragma unroll
            for (int j = 0; j < 2; j++) {
                wmma::fragment<wmma::matrix_b, 16, 16, 16, __half, wmma::row_major> bf;
                wmma::load_matrix_sync(bf, &Bs[kc * LDB + nbase + j * 16], LDB);
#pragma unroll
                for (int i = 0; i < 2; i++) {
                    wmma::mma_sync(acc[i][j], aH[i], bf, acc[i][j]);
                    wmma::mma_sync(acc[i][j], aL[i], bf, acc[i][j]);
                }
            }
        }
        __syncthreads();
    }

#pragma unroll
    for (int i = 0; i < 2; i++)
#pragma unroll
        for (int j = 0; j < 2; j++)
            wmma::store_matrix_sync(&ep[(mbase + i * 16) * BN + nbase + j * 16], acc[i][j], BN, wmma::mem_row_major);
    __syncthreads();
#pragma unroll
    for (int idx = tid; idx < 2048; idx += 256) {
        int row = idx >> 4, c4 = idx & 15;
        if (m0 + row < cnt)
            *(float4*)(d_y + (size_t)(off + m0 + row) * H + n0 + c4 * 4) = *(float4*)&ep[row * BN + c4 * 4];
    }
}

// ---------------- combine ----------------
__global__ __launch_bounds__(256) void combine_kernel(float* __restrict__ out) {
    int t = blockIdx.x;
    int p0 = d_token_pair[t * 4 + 0], p1 = d_token_pair[t * 4 + 1];
    int p2 = d_token_pair[t * 4 + 2], p3 = d_token_pair[t * 4 + 3];
    float w0 = d_pair_weight[p0], w1 = d_pair_weight[p1];
    float w2 = d_pair_weight[p2], w3 = d_pair_weight[p3];
    const float* y0 = d_y + (size_t)p0 * H;
    const float* y1 = d_y + (size_t)p1 * H;
    const float* y2 = d_y + (size_t)p2 * H;
    const float* y3 = d_y + (size_t)p3 * H;
    float* o = out + (size_t)t * H;
    for (int h = threadIdx.x; h < H; h += blockDim.x)
        o[h] = w0 * y0[h] + w1 * y1[h] + w2 * y2[h] + w3 * y3[h];
}

// ---------------- launch ----------------
extern "C" void kernel_launch(void* const* d_in, const int* in_sizes, int n_in,
                              void* d_out, int out_size) {
    const float* x      = (const float*)d_in[0];
    const float* gate_w = (const float*)d_in[1];
    const float* swg    = (const float*)d_in[2];
    const float* swu    = (const float*)d_in[3];
    const float* swd    = (const float*)d_in[4];
    const float* wg     = (const float*)d_in[5];
    const float* wu     = (const float*)d_in[6];
    const float* wd     = (const float*)d_in[7];
    float* out = (float*)d_out;

    cudaFuncSetAttribute(up_kernel,   cudaFuncAttributeMaxDynamicSharedMemorySize, UP_SMEM);
    cudaFuncSetAttribute(down_kernel, cudaFuncAttributeMaxDynamicSharedMemorySize, DN_SMEM);

    convert_all_kernel<<<4096, 256>>>((const float4*)wg, (const float4*)wu, (const float4*)wd,
                                      (const float4*)swg, (const float4*)swu, (const float4*)swd);

    init_kernel<<<1, 32>>>();
    router_kernel<<<NTOK / 8, 256>>>(x, gate_w);
    scan_kernel<<<1, 32>>>();
    build_pairs_kernel<<<NTOK / 256, 256>>>();
    gather_split_kernel<<<NPAIR, 192>>>(x);

    dim3 gUp(IDIM / BN, NTOK / BM, NEXP);     // (48, 16, 18)
    up_kernel<<<gUp, 256, UP_SMEM>>>();

    dim3 gDown(H / BN, NTOK / BM, NEXP);      // (12, 16, 18)
    down_kernel<<<gDown, 256, DN_SMEM>>>();

    combine_kernel<<<NTOK, 256>>>(out);
}

// round 8
// speedup vs baseline: 3.3804x; 1.1279x over previous
#include <cuda_runtime.h>
#include <cuda_fp16.h>
#include <mma.h>
#include <math.h>
#include <stdint.h>

using namespace nvcuda;

#define H     768
#define IDIM  3072
#define NE    16
#define NS    2
#define NEXP  (NE + NS)
#define NTOK  2048
#define KSEL  2
#define NPAIR (NTOK * 4)
#define ROUTED_PAIRS (NTOK * KSEL)

#define BM  128
#define BN  64
#define BK  32            // K per pipeline stage
#define LDK 40            // A smem row stride (fp16)
#define LDB 72            // B smem row stride (fp16)

// ---------------- persistent scratch ----------------
__device__ __half d_wg_h[(size_t)NE * H * IDIM];
__device__ __half d_wu_h[(size_t)NE * H * IDIM];
__device__ __half d_wd_h[(size_t)NE * IDIM * H];
__device__ __half d_sg_h[(size_t)NS * H * IDIM];
__device__ __half d_su_h[(size_t)NS * H * IDIM];
__device__ __half d_sd_h[(size_t)NS * IDIM * H];
__device__ __half d_xg_hi[(size_t)NPAIR * H];
__device__ __half d_xg_lo[(size_t)NPAIR * H];
__device__ __half d_act[(size_t)NPAIR * IDIM];      // plain fp16 activations
__device__ float d_y[(size_t)NPAIR * H];
__device__ int   d_pair_token[NPAIR];
__device__ float d_pair_weight[NPAIR];
__device__ int   d_token_pair[NTOK * 4];
__device__ int   d_cnt[NE];
__device__ int   d_fill[NE];
__device__ int   d_off[NEXP + 1];
__device__ int   d_tok_e[NTOK * KSEL];
__device__ float d_tok_w[NTOK * KSEL];

// ---------------- helpers ----------------
__device__ __forceinline__ void splitH4(float4 v, uint2& hi, uint2& lo) {
    float f[4] = {v.x, v.y, v.z, v.w};
    uint32_t h[4], l[4];
#pragma unroll
    for (int i = 0; i < 4; i++) {
        __half hb = __float2half_rn(f[i]);
        __half lb = __float2half_rn(f[i] - __half2float(hb));
        h[i] = (uint32_t)__half_as_ushort(hb);
        l[i] = (uint32_t)__half_as_ushort(lb);
    }
    hi = make_uint2(h[0] | (h[1] << 16), h[2] | (h[3] << 16));
    lo = make_uint2(l[0] | (l[1] << 16), l[2] | (l[3] << 16));
}
__device__ __forceinline__ uint2 cvtH4(float4 v) {
    uint32_t a = (uint32_t)__half_as_ushort(__float2half_rn(v.x))
               | ((uint32_t)__half_as_ushort(__float2half_rn(v.y)) << 16);
    uint32_t b = (uint32_t)__half_as_ushort(__float2half_rn(v.z))
               | ((uint32_t)__half_as_ushort(__float2half_rn(v.w)) << 16);
    return make_uint2(a, b);
}

__device__ __forceinline__ uint32_t smem_u32(const void* p) {
    uint32_t a;
    asm("{ .reg .u64 t; cvta.to.shared.u64 t, %1; cvt.u32.u64 %0, t; }" : "=r"(a) : "l"(p));
    return a;
}
__device__ __forceinline__ void cp16(uint32_t d, const void* s) {
    asm volatile("cp.async.cg.shared.global [%0], [%1], 16;" :: "r"(d), "l"(s) : "memory");
}
#define CP_COMMIT() asm volatile("cp.async.commit_group;" ::: "memory")
template<int N> __device__ __forceinline__ void cp_wait() {
    asm volatile("cp.async.wait_group %0;" :: "n"(N) : "memory");
}

// ---------------- routing ----------------
__global__ void init_kernel() {
    int t = threadIdx.x;
    if (t < NE) { d_cnt[t] = 0; d_fill[t] = 0; }
}

__global__ __launch_bounds__(256) void router_kernel(const float* __restrict__ x,
                                                     const float* __restrict__ gw) {
    int warp = (blockIdx.x * blockDim.x + threadIdx.x) >> 5;
    int lane = threadIdx.x & 31;
    if (warp >= NTOK) return;
    const float* xr = x + (size_t)warp * H;
    float acc[NE];
#pragma unroll
    for (int e = 0; e < NE; e++) acc[e] = 0.f;
    for (int h = lane; h < H; h += 32) {
        float xv = xr[h];
#pragma unroll
        for (int e = 0; e < NE; e++) acc[e] += xv * gw[e * H + h];
    }
#pragma unroll
    for (int e = 0; e < NE; e++) {
#pragma unroll
        for (int o = 16; o > 0; o >>= 1) acc[e] += __shfl_xor_sync(0xFFFFFFFFu, acc[e], o);
    }
    if (lane == 0) {
        float mx = acc[0];
#pragma unroll
        for (int e = 1; e < NE; e++) mx = fmaxf(mx, acc[e]);
        float p[NE]; float s = 0.f;
#pragma unroll
        for (int e = 0; e < NE; e++) { p[e] = expf(acc[e] - mx); s += p[e]; }
        float inv = 1.f / s;
#pragma unroll
        for (int e = 0; e < NE; e++) p[e] *= inv;
        int e0 = 0; float w0 = p[0];
        int e1 = -1; float w1 = -1.f;
#pragma unroll
        for (int e = 1; e < NE; e++) {
            if (p[e] > w0) { e1 = e0; w1 = w0; e0 = e; w0 = p[e]; }
            else if (p[e] > w1) { e1 = e; w1 = p[e]; }
        }
        float denom = w0 + w1 + 1e-8f;
        d_tok_e[warp * 2 + 0] = e0;  d_tok_w[warp * 2 + 0] = w0 / denom;
        d_tok_e[warp * 2 + 1] = e1;  d_tok_w[warp * 2 + 1] = w1 / denom;
        atomicAdd(&d_cnt[e0], 1);
        atomicAdd(&d_cnt[e1], 1);
    }
}

__global__ void scan_kernel() {
    if (threadIdx.x == 0) {
        int acc = 0;
        for (int e = 0; e < NE; e++) { d_off[e] = acc; acc += d_cnt[e]; }
        d_off[NE]     = ROUTED_PAIRS;
        d_off[NE + 1] = ROUTED_PAIRS + NTOK;
        d_off[NE + 2] = ROUTED_PAIRS + 2 * NTOK;
    }
}

__global__ void build_pairs_kernel() {
    int t = blockIdx.x * blockDim.x + threadIdx.x;
    if (t >= NTOK) return;
#pragma unroll
    for (int k = 0; k < KSEL; k++) {
        int e = d_tok_e[t * 2 + k];
        float w = d_tok_w[t * 2 + k];
        int pos = d_off[e] + atomicAdd(&d_fill[e], 1);
        d_pair_token[pos] = t;
        d_pair_weight[pos] = w;
        d_token_pair[t * 4 + k] = pos;
    }
#pragma unroll
    for (int s = 0; s < NS; s++) {
        int pos = ROUTED_PAIRS + s * NTOK + t;
        d_pair_token[pos] = t;
        d_pair_weight[pos] = 0.5f;
        d_token_pair[t * 4 + 2 + s] = pos;
    }
}

// ---------------- weight conversion to fp16 ----------------
__global__ __launch_bounds__(256) void convert_all_kernel(
    const float4* __restrict__ wg,  const float4* __restrict__ wu,  const float4* __restrict__ wd,
    const float4* __restrict__ swg, const float4* __restrict__ swu, const float4* __restrict__ swd) {
    const int NR  = NE * H * IDIM / 4;
    const int NSH = NS * H * IDIM / 4;
    const int total = 3 * NR + 3 * NSH;
    for (int i = blockIdx.x * blockDim.x + threadIdx.x; i < total;
         i += gridDim.x * blockDim.x) {
        const float4* src; uint2* dst; int idx;
        if (i < NR)                    { src = wg;  dst = (uint2*)d_wg_h; idx = i; }
        else if (i < 2 * NR)           { src = wu;  dst = (uint2*)d_wu_h; idx = i - NR; }
        else if (i < 3 * NR)           { src = wd;  dst = (uint2*)d_wd_h; idx = i - 2 * NR; }
        else if (i < 3 * NR + NSH)     { src = swg; dst = (uint2*)d_sg_h; idx = i - 3 * NR; }
        else if (i < 3 * NR + 2 * NSH) { src = swu; dst = (uint2*)d_su_h; idx = i - 3 * NR - NSH; }
        else                           { src = swd; dst = (uint2*)d_sd_h; idx = i - 3 * NR - 2 * NSH; }
        dst[idx] = cvtH4(__ldg(src + idx));
    }
}

// ---------------- gather + fp16 split of token rows ----------------
__global__ __launch_bounds__(192) void gather_split_kernel(const float* __restrict__ x) {
    int p = blockIdx.x;
    int t = threadIdx.x;
    int tok = d_pair_token[p];
    float4 v = *(const float4*)(x + (size_t)tok * H + t * 4);
    uint2 hi, lo;
    splitH4(v, hi, lo);
    *(uint2*)(d_xg_hi + (size_t)p * H + t * 4) = hi;
    *(uint2*)(d_xg_lo + (size_t)p * H + t * 4) = lo;
}

// ---------------- up/gate GEMM: fp16 A-split x2, cp.async double-buffered ----------------
#define ST_A   (BM * LDK * 2)            // 10240
#define ST_B1  (BK * LDB * 2)            // 4608
#define ST_UP  (2 * ST_A + 2 * ST_B1)    // 29696
#define UP_SMEM (2 * ST_UP)              // 59392

__global__ __launch_bounds__(256) void up_kernel() {
    int ez  = blockIdx.z;
    int off = d_off[ez];
    int cnt = d_off[ez + 1] - off;
    int m0  = blockIdx.y * BM;
    if (m0 >= cnt) return;
    int n0  = blockIdx.x * BN;

    const __half* Bg;
    const __half* Bu;
    if (ez < NE) {
        size_t wo = (size_t)ez * H * IDIM;
        Bg = d_wg_h + wo; Bu = d_wu_h + wo;
    } else {
        size_t wo = (size_t)(ez - NE) * H * IDIM;
        Bg = d_sg_h + wo; Bu = d_su_h + wo;
    }

    extern __shared__ char smraw[];
    uint32_t sb = smem_u32(smraw);
    float* ep = (float*)smraw;

    int tid = threadIdx.x, wid = tid >> 5;
    int mbase = (wid & 3) * 32;
    int nbase = (wid >> 2) * 32;

    wmma::fragment<wmma::accumulator, 16, 16, 16, float> accg[2][2], accu[2][2];
#pragma unroll
    for (int i = 0; i < 2; i++)
#pragma unroll
        for (int j = 0; j < 2; j++) { wmma::fill_fragment(accg[i][j], 0.f); wmma::fill_fragment(accu[i][j], 0.f); }

    auto load_stage = [&](int s, int k0) {
        uint32_t st = sb + s * ST_UP;
#pragma unroll
        for (int c = tid; c < 1536; c += 256) {
            if (c < 1024) {
                int split = c >> 9, row = (c >> 2) & 127, q = c & 3;
                int pr = off + min(m0 + row, cnt - 1);
                const __half* src = (split ? d_xg_lo : d_xg_hi) + (size_t)pr * H + k0 + q * 8;
                cp16(st + split * ST_A + row * (LDK * 2) + q * 16, src);
            } else {
                int b = c - 1024;
                int mat = b >> 8, r = (b >> 3) & 31, q = b & 7;
                const __half* src = (mat ? Bu : Bg) + (size_t)(k0 + r) * IDIM + n0 + q * 8;
                cp16(st + 2 * ST_A + mat * ST_B1 + r * (LDB * 2) + q * 16, src);
            }
        }
    };

    const int KT = H / BK;   // 24
    load_stage(0, 0);
    CP_COMMIT();

    for (int kt = 0; kt < KT; kt++) {
        if (kt + 1 < KT) { load_stage((kt + 1) & 1, (kt + 1) * BK); CP_COMMIT(); cp_wait<1>(); }
        else cp_wait<0>();
        __syncthreads();

        char* st = smraw + (kt & 1) * ST_UP;
        __half* AH = (__half*)st;
        __half* AL = (__half*)(st + ST_A);
        __half* BGs = (__half*)(st + 2 * ST_A);
        __half* BUs = (__half*)(st + 2 * ST_A + ST_B1);

#pragma unroll
        for (int ks = 0; ks < BK / 16; ks++) {
            int kc = ks * 16;
            wmma::fragment<wmma::matrix_a, 16, 16, 16, __half, wmma::row_major> aH[2], aL[2];
#pragma unroll
            for (int i = 0; i < 2; i++) {
                wmma::load_matrix_sync(aH[i], &AH[(mbase + i * 16) * LDK + kc], LDK);
                wmma::load_matrix_sync(aL[i], &AL[(mbase + i * 16) * LDK + kc], LDK);
            }
#pragma unroll
            for (int j = 0; j < 2; j++) {
                wmma::fragment<wmma::matrix_b, 16, 16, 16, __half, wmma::row_major> bg, bu;
                wmma::load_matrix_sync(bg, &BGs[kc * LDB + nbase + j * 16], LDB);
                wmma::load_matrix_sync(bu, &BUs[kc * LDB + nbase + j * 16], LDB);
#pragma unroll
                for (int i = 0; i < 2; i++) {
                    wmma::mma_sync(accg[i][j], aH[i], bg, accg[i][j]);
                    wmma::mma_sync(accg[i][j], aL[i], bg, accg[i][j]);
                    wmma::mma_sync(accu[i][j], aH[i], bu, accu[i][j]);
                    wmma::mma_sync(accu[i][j], aL[i], bu, accu[i][j]);
                }
            }
        }
        __syncthreads();
    }

    // epilogue: silu(g)*u -> plain fp16
#pragma unroll
    for (int i = 0; i < 2; i++)
#pragma unroll
        for (int j = 0; j < 2; j++) {
#pragma unroll
            for (int e = 0; e < accg[i][j].num_elements; e++) {
                float g = accg[i][j].x[e];
                float u = accu[i][j].x[e];
                accg[i][j].x[e] = (g / (1.f + expf(-g))) * u;
            }
            wmma::store_matrix_sync(&ep[(mbase + i * 16) * BN + nbase + j * 16], accg[i][j], BN, wmma::mem_row_major);
        }
    __syncthreads();
#pragma unroll
    for (int idx = tid; idx < 2048; idx += 256) {
        int row = idx >> 4, c4 = idx & 15;
        if (m0 + row < cnt) {
            float4 v = *(float4*)&ep[row * BN + c4 * 4];
            *(uint2*)(d_act + (size_t)(off + m0 + row) * IDIM + n0 + c4 * 4) = cvtH4(v);
        }
    }
}

// ---------------- down GEMM: plain fp16 x fp16 ----------------
#define ST_DN (ST_A + ST_B1)            // 14848
#define EP_BYTES (BM * BN * 4)          // 32768 (epilogue fp32 staging)
#define DN_SMEM ((2 * ST_DN) > EP_BYTES ? (2 * ST_DN) : EP_BYTES)   // 32768

__global__ __launch_bounds__(256) void down_kernel() {
    int ez  = blockIdx.z;
    int off = d_off[ez];
    int cnt = d_off[ez + 1] - off;
    int m0  = blockIdx.y * BM;
    if (m0 >= cnt) return;
    int n0  = blockIdx.x * BN;

    const __half* Bw = (ez < NE) ? d_wd_h + (size_t)ez * IDIM * H
                                 : d_sd_h + (size_t)(ez - NE) * IDIM * H;

    extern __shared__ char smraw[];
    uint32_t sb = smem_u32(smraw);
    float* ep = (float*)smraw;

    int tid = threadIdx.x, wid = tid >> 5;
    int mbase = (wid & 3) * 32;
    int nbase = (wid >> 2) * 32;

    wmma::fragment<wmma::accumulator, 16, 16, 16, float> acc[2][2];
#pragma unroll
    for (int i = 0; i < 2; i++)
#pragma unroll
        for (int j = 0; j < 2; j++) wmma::fill_fragment(acc[i][j], 0.f);

    auto load_stage = [&](int s, int k0) {
        uint32_t st = sb + s * ST_DN;
#pragma unroll
        for (int c = tid; c < 768; c += 256) {
            if (c < 512) {
                int row = c >> 2, q = c & 3;
                int pr = off + min(m0 + row, cnt - 1);
                const __half* src = d_act + (size_t)pr * IDIM + k0 + q * 8;
                cp16(st + row * (LDK * 2) + q * 16, src);
            } else {
                int b = c - 512;
                int r = b >> 3, q = b & 7;
                const __half* src = Bw + (size_t)(k0 + r) * H + n0 + q * 8;
                cp16(st + ST_A + r * (LDB * 2) + q * 16, src);
            }
        }
    };

    const int KT = IDIM / BK;   // 96
    load_stage(0, 0);
    CP_COMMIT();

    for (int kt = 0; kt < KT; kt++) {
        if (kt + 1 < KT) { load_stage((kt + 1) & 1, (kt + 1) * BK); CP_COMMIT(); cp_wait<1>(); }
        else cp_wait<0>();
        __syncthreads();

        char* st = smraw + (kt & 1) * ST_DN;
        __half* As = (__half*)st;
        __half* Bs = (__half*)(st + ST_A);

#pragma unroll
        for (int ks = 0; ks < BK / 16; ks++) {
            int kc = ks * 16;
            wmma::fragment<wmma::matrix_a, 16, 16, 16, __half, wmma::row_major> af[2];
#pragma unroll
            for (int i = 0; i < 2; i++)
                wmma::load_matrix_sync(af[i], &As[(mbase + i * 16) * LDK + kc], LDK);
#pragma unroll
            for (int j = 0; j < 2; j++) {
                wmma::fragment<wmma::matrix_b, 16, 16, 16, __half, wmma::row_major> bf;
                wmma::load_matrix_sync(bf, &Bs[kc * LDB + nbase + j * 16], LDB);
#pragma unroll
                for (int i = 0; i < 2; i++)
                    wmma::mma_sync(acc[i][j], af[i], bf, acc[i][j]);
            }
        }
        __syncthreads();
    }

#pragma unroll
    for (int i = 0; i < 2; i++)
#pragma unroll
        for (int j = 0; j < 2; j++)
            wmma::store_matrix_sync(&ep[(mbase + i * 16) * BN + nbase + j * 16], acc[i][j], BN, wmma::mem_row_major);
    __syncthreads();
#pragma unroll
    for (int idx = tid; idx < 2048; idx += 256) {
        int row = idx >> 4, c4 = idx & 15;
        if (m0 + row < cnt)
            *(float4*)(d_y + (size_t)(off + m0 + row) * H + n0 + c4 * 4) = *(float4*)&ep[row * BN + c4 * 4];
    }
}

// ---------------- combine ----------------
__global__ __launch_bounds__(256) void combine_kernel(float* __restrict__ out) {
    int t = blockIdx.x;
    int p0 = d_token_pair[t * 4 + 0], p1 = d_token_pair[t * 4 + 1];
    int p2 = d_token_pair[t * 4 + 2], p3 = d_token_pair[t * 4 + 3];
    float w0 = d_pair_weight[p0], w1 = d_pair_weight[p1];
    float w2 = d_pair_weight[p2], w3 = d_pair_weight[p3];
    const float* y0 = d_y + (size_t)p0 * H;
    const float* y1 = d_y + (size_t)p1 * H;
    const float* y2 = d_y + (size_t)p2 * H;
    const float* y3 = d_y + (size_t)p3 * H;
    float* o = out + (size_t)t * H;
    for (int h = threadIdx.x; h < H; h += blockDim.x)
        o[h] = w0 * y0[h] + w1 * y1[h] + w2 * y2[h] + w3 * y3[h];
}

// ---------------- launch ----------------
extern "C" void kernel_launch(void* const* d_in, const int* in_sizes, int n_in,
                              void* d_out, int out_size) {
    const float* x      = (const float*)d_in[0];
    const float* gate_w = (const float*)d_in[1];
    const float* swg    = (const float*)d_in[2];
    const float* swu    = (const float*)d_in[3];
    const float* swd    = (const float*)d_in[4];
    const float* wg     = (const float*)d_in[5];
    const float* wu     = (const float*)d_in[6];
    const float* wd     = (const float*)d_in[7];
    float* out = (float*)d_out;

    cudaFuncSetAttribute(up_kernel,   cudaFuncAttributeMaxDynamicSharedMemorySize, UP_SMEM);
    cudaFuncSetAttribute(down_kernel, cudaFuncAttributeMaxDynamicSharedMemorySize, DN_SMEM);

    convert_all_kernel<<<4096, 256>>>((const float4*)wg, (const float4*)wu, (const float4*)wd,
                                      (const float4*)swg, (const float4*)swu, (const float4*)swd);

    init_kernel<<<1, 32>>>();
    router_kernel<<<NTOK / 8, 256>>>(x, gate_w);
    scan_kernel<<<1, 32>>>();
    build_pairs_kernel<<<NTOK / 256, 256>>>();
    gather_split_kernel<<<NPAIR, 192>>>(x);

    dim3 gUp(IDIM / BN, NTOK / BM, NEXP);     // (48, 16, 18)
    up_kernel<<<gUp, 256, UP_SMEM>>>();

    dim3 gDown(H / BN, NTOK / BM, NEXP);      // (12, 16, 18)
    down_kernel<<<gDown, 256, DN_SMEM>>>();

    combine_kernel<<<NTOK, 256>>>(out);
}

// round 9
// speedup vs baseline: 4.2457x; 1.2560x over previous
#include <cuda_runtime.h>
#include <cuda_fp16.h>
#include <mma.h>
#include <math.h>
#include <stdint.h>

using namespace nvcuda;

#define H     768
#define IDIM  3072
#define NE    16
#define NS    2
#define NEXP  (NE + NS)
#define NTOK  2048
#define KSEL  2
#define NPAIR (NTOK * 4)
#define ROUTED_PAIRS (NTOK * KSEL)

#define BM  128
#define BN  64
#define BK  32            // K per pipeline stage
#define LDK 40            // A smem row stride (fp16)
#define LDB 72            // B smem row stride (fp16)

// ---------------- persistent scratch ----------------
__device__ __half d_wg_h[(size_t)NE * H * IDIM];
__device__ __half d_wu_h[(size_t)NE * H * IDIM];
__device__ __half d_wd_h[(size_t)NE * IDIM * H];
__device__ __half d_sg_h[(size_t)NS * H * IDIM];
__device__ __half d_su_h[(size_t)NS * H * IDIM];
__device__ __half d_sd_h[(size_t)NS * IDIM * H];
__device__ __half d_xg[(size_t)NPAIR * H];          // gathered fp16 token rows
__device__ __half d_act[(size_t)NPAIR * IDIM];      // fp16 activations
__device__ float d_y[(size_t)NPAIR * H];
__device__ int   d_pair_token[NPAIR];
__device__ float d_pair_weight[NPAIR];
__device__ int   d_token_pair[NTOK * 4];
__device__ int   d_cnt[NE];
__device__ int   d_fill[NE];
__device__ int   d_off[NEXP + 1];
__device__ int   d_tok_e[NTOK * KSEL];
__device__ float d_tok_w[NTOK * KSEL];

// ---------------- helpers ----------------
__device__ __forceinline__ uint2 cvtH4(float4 v) {
    uint32_t a = (uint32_t)__half_as_ushort(__float2half_rn(v.x))
               | ((uint32_t)__half_as_ushort(__float2half_rn(v.y)) << 16);
    uint32_t b = (uint32_t)__half_as_ushort(__float2half_rn(v.z))
               | ((uint32_t)__half_as_ushort(__float2half_rn(v.w)) << 16);
    return make_uint2(a, b);
}

__device__ __forceinline__ uint32_t smem_u32(const void* p) {
    uint32_t a;
    asm("{ .reg .u64 t; cvta.to.shared.u64 t, %1; cvt.u32.u64 %0, t; }" : "=r"(a) : "l"(p));
    return a;
}
__device__ __forceinline__ void cp16(uint32_t d, const void* s) {
    asm volatile("cp.async.cg.shared.global [%0], [%1], 16;" :: "r"(d), "l"(s) : "memory");
}
#define CP_COMMIT() asm volatile("cp.async.commit_group;" ::: "memory")
template<int N> __device__ __forceinline__ void cp_wait() {
    asm volatile("cp.async.wait_group %0;" :: "n"(N) : "memory");
}

// ---------------- routing ----------------
__global__ void init_kernel() {
    int t = threadIdx.x;
    if (t < NE) { d_cnt[t] = 0; d_fill[t] = 0; }
}

__global__ __launch_bounds__(256) void router_kernel(const float* __restrict__ x,
                                                     const float* __restrict__ gw) {
    int warp = (blockIdx.x * blockDim.x + threadIdx.x) >> 5;
    int lane = threadIdx.x & 31;
    if (warp >= NTOK) return;
    const float* xr = x + (size_t)warp * H;
    float acc[NE];
#pragma unroll
    for (int e = 0; e < NE; e++) acc[e] = 0.f;
    for (int h = lane; h < H; h += 32) {
        float xv = xr[h];
#pragma unroll
        for (int e = 0; e < NE; e++) acc[e] += xv * gw[e * H + h];
    }
#pragma unroll
    for (int e = 0; e < NE; e++) {
#pragma unroll
        for (int o = 16; o > 0; o >>= 1) acc[e] += __shfl_xor_sync(0xFFFFFFFFu, acc[e], o);
    }
    if (lane == 0) {
        float mx = acc[0];
#pragma unroll
        for (int e = 1; e < NE; e++) mx = fmaxf(mx, acc[e]);
        float p[NE]; float s = 0.f;
#pragma unroll
        for (int e = 0; e < NE; e++) { p[e] = expf(acc[e] - mx); s += p[e]; }
        float inv = 1.f / s;
#pragma unroll
        for (int e = 0; e < NE; e++) p[e] *= inv;
        int e0 = 0; float w0 = p[0];
        int e1 = -1; float w1 = -1.f;
#pragma unroll
        for (int e = 1; e < NE; e++) {
            if (p[e] > w0) { e1 = e0; w1 = w0; e0 = e; w0 = p[e]; }
            else if (p[e] > w1) { e1 = e; w1 = p[e]; }
        }
        float denom = w0 + w1 + 1e-8f;
        d_tok_e[warp * 2 + 0] = e0;  d_tok_w[warp * 2 + 0] = w0 / denom;
        d_tok_e[warp * 2 + 1] = e1;  d_tok_w[warp * 2 + 1] = w1 / denom;
        atomicAdd(&d_cnt[e0], 1);
        atomicAdd(&d_cnt[e1], 1);
    }
}

__global__ void scan_kernel() {
    if (threadIdx.x == 0) {
        int acc = 0;
        for (int e = 0; e < NE; e++) { d_off[e] = acc; acc += d_cnt[e]; }
        d_off[NE]     = ROUTED_PAIRS;
        d_off[NE + 1] = ROUTED_PAIRS + NTOK;
        d_off[NE + 2] = ROUTED_PAIRS + 2 * NTOK;
    }
}

__global__ void build_pairs_kernel() {
    int t = blockIdx.x * blockDim.x + threadIdx.x;
    if (t >= NTOK) return;
#pragma unroll
    for (int k = 0; k < KSEL; k++) {
        int e = d_tok_e[t * 2 + k];
        float w = d_tok_w[t * 2 + k];
        int pos = d_off[e] + atomicAdd(&d_fill[e], 1);
        d_pair_token[pos] = t;
        d_pair_weight[pos] = w;
        d_token_pair[t * 4 + k] = pos;
    }
#pragma unroll
    for (int s = 0; s < NS; s++) {
        int pos = ROUTED_PAIRS + s * NTOK + t;
        d_pair_token[pos] = t;
        d_pair_weight[pos] = 0.5f;
        d_token_pair[t * 4 + 2 + s] = pos;
    }
}

// ---------------- weight conversion to fp16 ----------------
__global__ __launch_bounds__(256) void convert_all_kernel(
    const float4* __restrict__ wg,  const float4* __restrict__ wu,  const float4* __restrict__ wd,
    const float4* __restrict__ swg, const float4* __restrict__ swu, const float4* __restrict__ swd) {
    const int NR  = NE * H * IDIM / 4;
    const int NSH = NS * H * IDIM / 4;
    const int total = 3 * NR + 3 * NSH;
    for (int i = blockIdx.x * blockDim.x + threadIdx.x; i < total;
         i += gridDim.x * blockDim.x) {
        const float4* src; uint2* dst; int idx;
        if (i < NR)                    { src = wg;  dst = (uint2*)d_wg_h; idx = i; }
        else if (i < 2 * NR)           { src = wu;  dst = (uint2*)d_wu_h; idx = i - NR; }
        else if (i < 3 * NR)           { src = wd;  dst = (uint2*)d_wd_h; idx = i - 2 * NR; }
        else if (i < 3 * NR + NSH)     { src = swg; dst = (uint2*)d_sg_h; idx = i - 3 * NR; }
        else if (i < 3 * NR + 2 * NSH) { src = swu; dst = (uint2*)d_su_h; idx = i - 3 * NR - NSH; }
        else                           { src = swd; dst = (uint2*)d_sd_h; idx = i - 3 * NR - 2 * NSH; }
        dst[idx] = cvtH4(__ldg(src + idx));
    }
}

// ---------------- gather token rows -> fp16 ----------------
__global__ __launch_bounds__(192) void gather_kernel(const float* __restrict__ x) {
    int p = blockIdx.x;
    int t = threadIdx.x;
    int tok = d_pair_token[p];
    float4 v = *(const float4*)(x + (size_t)tok * H + t * 4);
    *(uint2*)(d_xg + (size_t)p * H + t * 4) = cvtH4(v);
}

// ---------------- up/gate GEMM: fp16, cp.async double-buffered ----------------
#define ST_A   (BM * LDK * 2)            // 10240
#define ST_B1  (BK * LDB * 2)            // 4608
#define ST_UP  (ST_A + 2 * ST_B1)        // 19456
#define UP_SMEM (2 * ST_UP)              // 38912 (>= 32768 epilogue)

__global__ __launch_bounds__(256) void up_kernel() {
    int ez  = blockIdx.z;
    int off = d_off[ez];
    int cnt = d_off[ez + 1] - off;
    int m0  = blockIdx.y * BM;
    if (m0 >= cnt) return;
    int n0  = blockIdx.x * BN;

    const __half* Bg;
    const __half* Bu;
    if (ez < NE) {
        size_t wo = (size_t)ez * H * IDIM;
        Bg = d_wg_h + wo; Bu = d_wu_h + wo;
    } else {
        size_t wo = (size_t)(ez - NE) * H * IDIM;
        Bg = d_sg_h + wo; Bu = d_su_h + wo;
    }

    extern __shared__ char smraw[];
    uint32_t sb = smem_u32(smraw);
    float* ep = (float*)smraw;

    int tid = threadIdx.x, wid = tid >> 5;
    int mbase = (wid & 3) * 32;
    int nbase = (wid >> 2) * 32;

    wmma::fragment<wmma::accumulator, 16, 16, 16, float> accg[2][2], accu[2][2];
#pragma unroll
    for (int i = 0; i < 2; i++)
#pragma unroll
        for (int j = 0; j < 2; j++) { wmma::fill_fragment(accg[i][j], 0.f); wmma::fill_fragment(accu[i][j], 0.f); }

    // 1024 16B chunks: A 512, Bg/Bu 512
    auto load_stage = [&](int s, int k0) {
        uint32_t st = sb + s * ST_UP;
#pragma unroll
        for (int c = tid; c < 1024; c += 256) {
            if (c < 512) {
                int row = c >> 2, q = c & 3;
                int pr = off + min(m0 + row, cnt - 1);
                const __half* src = d_xg + (size_t)pr * H + k0 + q * 8;
                cp16(st + row * (LDK * 2) + q * 16, src);
            } else {
                int b = c - 512;
                int mat = b >> 8, r = (b >> 3) & 31, q = b & 7;
                const __half* src = (mat ? Bu : Bg) + (size_t)(k0 + r) * IDIM + n0 + q * 8;
                cp16(st + ST_A + mat * ST_B1 + r * (LDB * 2) + q * 16, src);
            }
        }
    };

    const int KT = H / BK;   // 24
    load_stage(0, 0);
    CP_COMMIT();

    for (int kt = 0; kt < KT; kt++) {
        if (kt + 1 < KT) { load_stage((kt + 1) & 1, (kt + 1) * BK); CP_COMMIT(); cp_wait<1>(); }
        else cp_wait<0>();
        __syncthreads();

        char* st = smraw + (kt & 1) * ST_UP;
        __half* As  = (__half*)st;
        __half* BGs = (__half*)(st + ST_A);
        __half* BUs = (__half*)(st + ST_A + ST_B1);

#pragma unroll
        for (int ks = 0; ks < BK / 16; ks++) {
            int kc = ks * 16;
            wmma::fragment<wmma::matrix_a, 16, 16, 16, __half, wmma::row_major> af[2];
#pragma unroll
            for (int i = 0; i < 2; i++)
                wmma::load_matrix_sync(af[i], &As[(mbase + i * 16) * LDK + kc], LDK);
#pragma unroll
            for (int j = 0; j < 2; j++) {
                wmma::fragment<wmma::matrix_b, 16, 16, 16, __half, wmma::row_major> bg, bu;
                wmma::load_matrix_sync(bg, &BGs[kc * LDB + nbase + j * 16], LDB);
                wmma::load_matrix_sync(bu, &BUs[kc * LDB + nbase + j * 16], LDB);
#pragma unroll
                for (int i = 0; i < 2; i++) {
                    wmma::mma_sync(accg[i][j], af[i], bg, accg[i][j]);
                    wmma::mma_sync(accu[i][j], af[i], bu, accu[i][j]);
                }
            }
        }
        __syncthreads();
    }

    // epilogue: silu(g)*u -> plain fp16
#pragma unroll
    for (int i = 0; i < 2; i++)
#pragma unroll
        for (int j = 0; j < 2; j++) {
#pragma unroll
            for (int e = 0; e < accg[i][j].num_elements; e++) {
                float g = accg[i][j].x[e];
                float u = accu[i][j].x[e];
                accg[i][j].x[e] = (g / (1.f + expf(-g))) * u;
            }
            wmma::store_matrix_sync(&ep[(mbase + i * 16) * BN + nbase + j * 16], accg[i][j], BN, wmma::mem_row_major);
        }
    __syncthreads();
#pragma unroll
    for (int idx = tid; idx < 2048; idx += 256) {
        int row = idx >> 4, c4 = idx & 15;
        if (m0 + row < cnt) {
            float4 v = *(float4*)&ep[row * BN + c4 * 4];
            *(uint2*)(d_act + (size_t)(off + m0 + row) * IDIM + n0 + c4 * 4) = cvtH4(v);
        }
    }
}

// ---------------- down GEMM: plain fp16 x fp16 ----------------
#define ST_DN (ST_A + ST_B1)            // 14848
#define EP_BYTES (BM * BN * 4)          // 32768
#define DN_SMEM ((2 * ST_DN) > EP_BYTES ? (2 * ST_DN) : EP_BYTES)   // 32768

__global__ __launch_bounds__(256) void down_kernel() {
    int ez  = blockIdx.z;
    int off = d_off[ez];
    int cnt = d_off[ez + 1] - off;
    int m0  = blockIdx.y * BM;
    if (m0 >= cnt) return;
    int n0  = blockIdx.x * BN;

    const __half* Bw = (ez < NE) ? d_wd_h + (size_t)ez * IDIM * H
                                 : d_sd_h + (size_t)(ez - NE) * IDIM * H;

    extern __shared__ char smraw[];
    uint32_t sb = smem_u32(smraw);
    float* ep = (float*)smraw;

    int tid = threadIdx.x, wid = tid >> 5;
    int mbase = (wid & 3) * 32;
    int nbase = (wid >> 2) * 32;

    wmma::fragment<wmma::accumulator, 16, 16, 16, float> acc[2][2];
#pragma unroll
    for (int i = 0; i < 2; i++)
#pragma unroll
        for (int j = 0; j < 2; j++) wmma::fill_fragment(acc[i][j], 0.f);

    auto load_stage = [&](int s, int k0) {
        uint32_t st = sb + s * ST_DN;
#pragma unroll
        for (int c = tid; c < 768; c += 256) {
            if (c < 512) {
                int row = c >> 2, q = c & 3;
                int pr = off + min(m0 + row, cnt - 1);
                const __half* src = d_act + (size_t)pr * IDIM + k0 + q * 8;
                cp16(st + row * (LDK * 2) + q * 16, src);
            } else {
                int b = c - 512;
                int r = b >> 3, q = b & 7;
                const __half* src = Bw + (size_t)(k0 + r) * H + n0 + q * 8;
                cp16(st + ST_A + r * (LDB * 2) + q * 16, src);
            }
        }
    };

    const int KT = IDIM / BK;   // 96
    load_stage(0, 0);
    CP_COMMIT();

    for (int kt = 0; kt < KT; kt++) {
        if (kt + 1 < KT) { load_stage((kt + 1) & 1, (kt + 1) * BK); CP_COMMIT(); cp_wait<1>(); }
        else cp_wait<0>();
        __syncthreads();

        char* st = smraw + (kt & 1) * ST_DN;
        __half* As = (__half*)st;
        __half* Bs = (__half*)(st + ST_A);

#pragma unroll
        for (int ks = 0; ks < BK / 16; ks++) {
            int kc = ks * 16;
            wmma::fragment<wmma::matrix_a, 16, 16, 16, __half, wmma::row_major> af[2];
#pragma unroll
            for (int i = 0; i < 2; i++)
                wmma::load_matrix_sync(af[i], &As[(mbase + i * 16) * LDK + kc], LDK);
#pragma unroll
            for (int j = 0; j < 2; j++) {
                wmma::fragment<wmma::matrix_b, 16, 16, 16, __half, wmma::row_major> bf;
                wmma::load_matrix_sync(bf, &Bs[kc * LDB + nbase + j * 16], LDB);
#pragma unroll
                for (int i = 0; i < 2; i++)
                    wmma::mma_sync(acc[i][j], af[i], bf, acc[i][j]);
            }
        }
        __syncthreads();
    }

#pragma unroll
    for (int i = 0; i < 2; i++)
#pragma unroll
        for (int j = 0; j < 2; j++)
            wmma::store_matrix_sync(&ep[(mbase + i * 16) * BN + nbase + j * 16], acc[i][j], BN, wmma::mem_row_major);
    __syncthreads();
#pragma unroll
    for (int idx = tid; idx < 2048; idx += 256) {
        int row = idx >> 4, c4 = idx & 15;
        if (m0 + row < cnt)
            *(float4*)(d_y + (size_t)(off + m0 + row) * H + n0 + c4 * 4) = *(float4*)&ep[row * BN + c4 * 4];
    }
}

// ---------------- combine ----------------
__global__ __launch_bounds__(256) void combine_kernel(float* __restrict__ out) {
    int t = blockIdx.x;
    int p0 = d_token_pair[t * 4 + 0], p1 = d_token_pair[t * 4 + 1];
    int p2 = d_token_pair[t * 4 + 2], p3 = d_token_pair[t * 4 + 3];
    float w0 = d_pair_weight[p0], w1 = d_pair_weight[p1];
    float w2 = d_pair_weight[p2], w3 = d_pair_weight[p3];
    const float* y0 = d_y + (size_t)p0 * H;
    const float* y1 = d_y + (size_t)p1 * H;
    const float* y2 = d_y + (size_t)p2 * H;
    const float* y3 = d_y + (size_t)p3 * H;
    float* o = out + (size_t)t * H;
    for (int h = threadIdx.x; h < H; h += blockDim.x)
        o[h] = w0 * y0[h] + w1 * y1[h] + w2 * y2[h] + w3 * y3[h];
}

// ---------------- launch ----------------
extern "C" void kernel_launch(void* const* d_in, const int* in_sizes, int n_in,
                              void* d_out, int out_size) {
    const float* x      = (const float*)d_in[0];
    const float* gate_w = (const float*)d_in[1];
    const float* swg    = (const float*)d_in[2];
    const float* swu    = (const float*)d_in[3];
    const float* swd    = (const float*)d_in[4];
    const float* wg     = (const float*)d_in[5];
    const float* wu     = (const float*)d_in[6];
    const float* wd     = (const float*)d_in[7];
    float* out = (float*)d_out;

    cudaFuncSetAttribute(up_kernel,   cudaFuncAttributeMaxDynamicSharedMemorySize, UP_SMEM);
    cudaFuncSetAttribute(down_kernel, cudaFuncAttributeMaxDynamicSharedMemorySize, DN_SMEM);

    convert_all_kernel<<<4096, 256>>>((const float4*)wg, (const float4*)wu, (const float4*)wd,
                                      (const float4*)swg, (const float4*)swu, (const float4*)swd);

    init_kernel<<<1, 32>>>();
    router_kernel<<<NTOK / 8, 256>>>(x, gate_w);
    scan_kernel<<<1, 32>>>();
    build_pairs_kernel<<<NTOK / 256, 256>>>();
    gather_kernel<<<NPAIR, 192>>>(x);

    dim3 gUp(IDIM / BN, NTOK / BM, NEXP);     // (48, 16, 18)
    up_kernel<<<gUp, 256, UP_SMEM>>>();

    dim3 gDown(H / BN, NTOK / BM, NEXP);      // (12, 16, 18)
    down_kernel<<<gDown, 256, DN_SMEM>>>();

    combine_kernel<<<NTOK, 256>>>(out);
}

// round 10
// speedup vs baseline: 4.7449x; 1.1176x over previous
#include <cuda_runtime.h>
#include <cuda_fp16.h>
#include <mma.h>
#include <math.h>
#include <stdint.h>

using namespace nvcuda;

#define H     768
#define IDIM  3072
#define NE    16
#define NS    2
#define NEXP  (NE + NS)
#define NTOK  2048
#define KSEL  2
#define NPAIR (NTOK * 4)
#define ROUTED_PAIRS (NTOK * KSEL)

#define BM  128
#define BN  64
#define BK  64            // K per pipeline stage (doubled vs R9)
#define LDK 72            // A smem row stride (fp16): BK + 8 pad
#define LDB 72            // B smem row stride (fp16): BN + 8 pad

// ---------------- persistent scratch ----------------
__device__ __half d_wg_h[(size_t)NE * H * IDIM];
__device__ __half d_wu_h[(size_t)NE * H * IDIM];
__device__ __half d_wd_h[(size_t)NE * IDIM * H];
__device__ __half d_sg_h[(size_t)NS * H * IDIM];
__device__ __half d_su_h[(size_t)NS * H * IDIM];
__device__ __half d_sd_h[(size_t)NS * IDIM * H];
__device__ __half d_xg[(size_t)NPAIR * H];          // gathered fp16 token rows
__device__ __half d_act[(size_t)NPAIR * IDIM];      // fp16 activations
__device__ float d_y[(size_t)NPAIR * H];
__device__ int   d_pair_token[NPAIR];
__device__ float d_pair_weight[NPAIR];
__device__ int   d_token_pair[NTOK * 4];
__device__ int   d_cnt[NE];
__device__ int   d_fill[NE];
__device__ int   d_off[NEXP + 1];
__device__ int   d_tok_e[NTOK * KSEL];
__device__ float d_tok_w[NTOK * KSEL];

// ---------------- helpers ----------------
__device__ __forceinline__ uint2 cvtH4(float4 v) {
    uint32_t a = (uint32_t)__half_as_ushort(__float2half_rn(v.x))
               | ((uint32_t)__half_as_ushort(__float2half_rn(v.y)) << 16);
    uint32_t b = (uint32_t)__half_as_ushort(__float2half_rn(v.z))
               | ((uint32_t)__half_as_ushort(__float2half_rn(v.w)) << 16);
    return make_uint2(a, b);
}

__device__ __forceinline__ uint32_t smem_u32(const void* p) {
    uint32_t a;
    asm("{ .reg .u64 t; cvta.to.shared.u64 t, %1; cvt.u32.u64 %0, t; }" : "=r"(a) : "l"(p));
    return a;
}
__device__ __forceinline__ void cp16(uint32_t d, const void* s) {
    asm volatile("cp.async.cg.shared.global [%0], [%1], 16;" :: "r"(d), "l"(s) : "memory");
}
#define CP_COMMIT() asm volatile("cp.async.commit_group;" ::: "memory")
template<int N> __device__ __forceinline__ void cp_wait() {
    asm volatile("cp.async.wait_group %0;" :: "n"(N) : "memory");
}

// ---------------- routing ----------------
__global__ void init_kernel() {
    int t = threadIdx.x;
    if (t < NE) { d_cnt[t] = 0; d_fill[t] = 0; }
}

__global__ __launch_bounds__(256) void router_kernel(const float* __restrict__ x,
                                                     const float* __restrict__ gw) {
    int warp = (blockIdx.x * blockDim.x + threadIdx.x) >> 5;
    int lane = threadIdx.x & 31;
    if (warp >= NTOK) return;
    const float* xr = x + (size_t)warp * H;
    float acc[NE];
#pragma unroll
    for (int e = 0; e < NE; e++) acc[e] = 0.f;
    for (int h = lane; h < H; h += 32) {
        float xv = xr[h];
#pragma unroll
        for (int e = 0; e < NE; e++) acc[e] += xv * gw[e * H + h];
    }
#pragma unroll
    for (int e = 0; e < NE; e++) {
#pragma unroll
        for (int o = 16; o > 0; o >>= 1) acc[e] += __shfl_xor_sync(0xFFFFFFFFu, acc[e], o);
    }
    if (lane == 0) {
        float mx = acc[0];
#pragma unroll
        for (int e = 1; e < NE; e++) mx = fmaxf(mx, acc[e]);
        float p[NE]; float s = 0.f;
#pragma unroll
        for (int e = 0; e < NE; e++) { p[e] = expf(acc[e] - mx); s += p[e]; }
        float inv = 1.f / s;
#pragma unroll
        for (int e = 0; e < NE; e++) p[e] *= inv;
        int e0 = 0; float w0 = p[0];
        int e1 = -1; float w1 = -1.f;
#pragma unroll
        for (int e = 1; e < NE; e++) {
            if (p[e] > w0) { e1 = e0; w1 = w0; e0 = e; w0 = p[e]; }
            else if (p[e] > w1) { e1 = e; w1 = p[e]; }
        }
        float denom = w0 + w1 + 1e-8f;
        d_tok_e[warp * 2 + 0] = e0;  d_tok_w[warp * 2 + 0] = w0 / denom;
        d_tok_e[warp * 2 + 1] = e1;  d_tok_w[warp * 2 + 1] = w1 / denom;
        atomicAdd(&d_cnt[e0], 1);
        atomicAdd(&d_cnt[e1], 1);
    }
}

__global__ void scan_kernel() {
    if (threadIdx.x == 0) {
        int acc = 0;
        for (int e = 0; e < NE; e++) { d_off[e] = acc; acc += d_cnt[e]; }
        d_off[NE]     = ROUTED_PAIRS;
        d_off[NE + 1] = ROUTED_PAIRS + NTOK;
        d_off[NE + 2] = ROUTED_PAIRS + 2 * NTOK;
    }
}

__global__ void build_pairs_kernel() {
    int t = blockIdx.x * blockDim.x + threadIdx.x;
    if (t >= NTOK) return;
#pragma unroll
    for (int k = 0; k < KSEL; k++) {
        int e = d_tok_e[t * 2 + k];
        float w = d_tok_w[t * 2 + k];
        int pos = d_off[e] + atomicAdd(&d_fill[e], 1);
        d_pair_token[pos] = t;
        d_pair_weight[pos] = w;
        d_token_pair[t * 4 + k] = pos;
    }
#pragma unroll
    for (int s = 0; s < NS; s++) {
        int pos = ROUTED_PAIRS + s * NTOK + t;
        d_pair_token[pos] = t;
        d_pair_weight[pos] = 0.5f;
        d_token_pair[t * 4 + 2 + s] = pos;
    }
}

// ---------------- weight conversion to fp16 ----------------
__global__ __launch_bounds__(256) void convert_all_kernel(
    const float4* __restrict__ wg,  const float4* __restrict__ wu,  const float4* __restrict__ wd,
    const float4* __restrict__ swg, const float4* __restrict__ swu, const float4* __restrict__ swd) {
    const int NR  = NE * H * IDIM / 4;
    const int NSH = NS * H * IDIM / 4;
    const int total = 3 * NR + 3 * NSH;
    for (int i = blockIdx.x * blockDim.x + threadIdx.x; i < total;
         i += gridDim.x * blockDim.x) {
        const float4* src; uint2* dst; int idx;
        if (i < NR)                    { src = wg;  dst = (uint2*)d_wg_h; idx = i; }
        else if (i < 2 * NR)           { src = wu;  dst = (uint2*)d_wu_h; idx = i - NR; }
        else if (i < 3 * NR)           { src = wd;  dst = (uint2*)d_wd_h; idx = i - 2 * NR; }
        else if (i < 3 * NR + NSH)     { src = swg; dst = (uint2*)d_sg_h; idx = i - 3 * NR; }
        else if (i < 3 * NR + 2 * NSH) { src = swu; dst = (uint2*)d_su_h; idx = i - 3 * NR - NSH; }
        else                           { src = swd; dst = (uint2*)d_sd_h; idx = i - 3 * NR - 2 * NSH; }
        dst[idx] = cvtH4(__ldg(src + idx));
    }
}

// ---------------- gather token rows -> fp16 ----------------
__global__ __launch_bounds__(192) void gather_kernel(const float* __restrict__ x) {
    int p = blockIdx.x;
    int t = threadIdx.x;
    int tok = d_pair_token[p];
    float4 v = *(const float4*)(x + (size_t)tok * H + t * 4);
    *(uint2*)(d_xg + (size_t)p * H + t * 4) = cvtH4(v);
}

// ---------------- up/gate GEMM: fp16, BK=64, cp.async double-buffered ----------------
#define ST_A   (BM * LDK * 2)            // 18432
#define ST_B1  (BK * LDB * 2)            // 9216
#define ST_UP  (ST_A + 2 * ST_B1)        // 36864
#define UP_SMEM (2 * ST_UP)              // 73728

__global__ __launch_bounds__(256) void up_kernel() {
    int ez  = blockIdx.z;
    int off = d_off[ez];
    int cnt = d_off[ez + 1] - off;
    int m0  = blockIdx.y * BM;
    if (m0 >= cnt) return;
    int n0  = blockIdx.x * BN;

    const __half* Bg;
    const __half* Bu;
    if (ez < NE) {
        size_t wo = (size_t)ez * H * IDIM;
        Bg = d_wg_h + wo; Bu = d_wu_h + wo;
    } else {
        size_t wo = (size_t)(ez - NE) * H * IDIM;
        Bg = d_sg_h + wo; Bu = d_su_h + wo;
    }

    extern __shared__ char smraw[];
    uint32_t sb = smem_u32(smraw);
    float* ep = (float*)smraw;

    int tid = threadIdx.x, wid = tid >> 5;
    int mbase = (wid & 3) * 32;
    int nbase = (wid >> 2) * 32;

    wmma::fragment<wmma::accumulator, 16, 16, 16, float> accg[2][2], accu[2][2];
#pragma unroll
    for (int i = 0; i < 2; i++)
#pragma unroll
        for (int j = 0; j < 2; j++) { wmma::fill_fragment(accg[i][j], 0.f); wmma::fill_fragment(accu[i][j], 0.f); }

    // 2048 16B chunks: A 1024 (128 rows x 8), Bg/Bu 512 each (64 rows x 8)
    auto load_stage = [&](int s, int k0) {
        uint32_t st = sb + s * ST_UP;
#pragma unroll
        for (int c = tid; c < 2048; c += 256) {
            if (c < 1024) {
                int row = c >> 3, q = c & 7;
                int pr = off + min(m0 + row, cnt - 1);
                const __half* src = d_xg + (size_t)pr * H + k0 + q * 8;
                cp16(st + row * (LDK * 2) + q * 16, src);
            } else {
                int b = c - 1024;
                int mat = b >> 9, r = (b >> 3) & 63, q = b & 7;
                const __half* src = (mat ? Bu : Bg) + (size_t)(k0 + r) * IDIM + n0 + q * 8;
                cp16(st + ST_A + mat * ST_B1 + r * (LDB * 2) + q * 16, src);
            }
        }
    };

    const int KT = H / BK;   // 12
    load_stage(0, 0);
    CP_COMMIT();

    for (int kt = 0; kt < KT; kt++) {
        if (kt + 1 < KT) { load_stage((kt + 1) & 1, (kt + 1) * BK); CP_COMMIT(); cp_wait<1>(); }
        else cp_wait<0>();
        __syncthreads();

        char* st = smraw + (kt & 1) * ST_UP;
        __half* As  = (__half*)st;
        __half* BGs = (__half*)(st + ST_A);
        __half* BUs = (__half*)(st + ST_A + ST_B1);

#pragma unroll
        for (int ks = 0; ks < BK / 16; ks++) {
            int kc = ks * 16;
            wmma::fragment<wmma::matrix_a, 16, 16, 16, __half, wmma::row_major> af[2];
#pragma unroll
            for (int i = 0; i < 2; i++)
                wmma::load_matrix_sync(af[i], &As[(mbase + i * 16) * LDK + kc], LDK);
#pragma unroll
            for (int j = 0; j < 2; j++) {
                wmma::fragment<wmma::matrix_b, 16, 16, 16, __half, wmma::row_major> bg, bu;
                wmma::load_matrix_sync(bg, &BGs[kc * LDB + nbase + j * 16], LDB);
                wmma::load_matrix_sync(bu, &BUs[kc * LDB + nbase + j * 16], LDB);
#pragma unroll
                for (int i = 0; i < 2; i++) {
                    wmma::mma_sync(accg[i][j], af[i], bg, accg[i][j]);
                    wmma::mma_sync(accu[i][j], af[i], bu, accu[i][j]);
                }
            }
        }
        __syncthreads();
    }

    // epilogue: silu(g)*u -> plain fp16
#pragma unroll
    for (int i = 0; i < 2; i++)
#pragma unroll
        for (int j = 0; j < 2; j++) {
#pragma unroll
            for (int e = 0; e < accg[i][j].num_elements; e++) {
                float g = accg[i][j].x[e];
                float u = accu[i][j].x[e];
                accg[i][j].x[e] = (g / (1.f + expf(-g))) * u;
            }
            wmma::store_matrix_sync(&ep[(mbase + i * 16) * BN + nbase + j * 16], accg[i][j], BN, wmma::mem_row_major);
        }
    __syncthreads();
#pragma unroll
    for (int idx = tid; idx < 2048; idx += 256) {
        int row = idx >> 4, c4 = idx & 15;
        if (m0 + row < cnt) {
            float4 v = *(float4*)&ep[row * BN + c4 * 4];
            *(uint2*)(d_act + (size_t)(off + m0 + row) * IDIM + n0 + c4 * 4) = cvtH4(v);
        }
    }
}

// ---------------- down GEMM: plain fp16 x fp16, BK=64 ----------------
#define ST_DN (ST_A + ST_B1)            // 27648
#define EP_BYTES (BM * BN * 4)          // 32768
#define DN_SMEM ((2 * ST_DN) > EP_BYTES ? (2 * ST_DN) : EP_BYTES)   // 55296

__global__ __launch_bounds__(256) void down_kernel() {
    int ez  = blockIdx.z;
    int off = d_off[ez];
    int cnt = d_off[ez + 1] - off;
    int m0  = blockIdx.y * BM;
    if (m0 >= cnt) return;
    int n0  = blockIdx.x * BN;

    const __half* Bw = (ez < NE) ? d_wd_h + (size_t)ez * IDIM * H
                                 : d_sd_h + (size_t)(ez - NE) * IDIM * H;

    extern __shared__ char smraw[];
    uint32_t sb = smem_u32(smraw);
    float* ep = (float*)smraw;

    int tid = threadIdx.x, wid = tid >> 5;
    int mbase = (wid & 3) * 32;
    int nbase = (wid >> 2) * 32;

    wmma::fragment<wmma::accumulator, 16, 16, 16, float> acc[2][2];
#pragma unroll
    for (int i = 0; i < 2; i++)
#pragma unroll
        for (int j = 0; j < 2; j++) wmma::fill_fragment(acc[i][j], 0.f);

    // 1536 chunks: A 1024, B 512
    auto load_stage = [&](int s, int k0) {
        uint32_t st = sb + s * ST_DN;
#pragma unroll
        for (int c = tid; c < 1536; c += 256) {
            if (c < 1024) {
                int row = c >> 3, q = c & 7;
                int pr = off + min(m0 + row, cnt - 1);
                const __half* src = d_act + (size_t)pr * IDIM + k0 + q * 8;
                cp16(st + row * (LDK * 2) + q * 16, src);
            } else {
                int b = c - 1024;
                int r = b >> 3, q = b & 7;
                const __half* src = Bw + (size_t)(k0 + r) * H + n0 + q * 8;
                cp16(st + ST_A + r * (LDB * 2) + q * 16, src);
            }
        }
    };

    const int KT = IDIM / BK;   // 48
    load_stage(0, 0);
    CP_COMMIT();

    for (int kt = 0; kt < KT; kt++) {
        if (kt + 1 < KT) { load_stage((kt + 1) & 1, (kt + 1) * BK); CP_COMMIT(); cp_wait<1>(); }
        else cp_wait<0>();
        __syncthreads();

        char* st = smraw + (kt & 1) * ST_DN;
        __half* As = (__half*)st;
        __half* Bs = (__half*)(st + ST_A);

#pragma unroll
        for (int ks = 0; ks < BK / 16; ks++) {
            int kc = ks * 16;
            wmma::fragment<wmma::matrix_a, 16, 16, 16, __half, wmma::row_major> af[2];
#pragma unroll
            for (int i = 0; i < 2; i++)
                wmma::load_matrix_sync(af[i], &As[(mbase + i * 16) * LDK + kc], LDK);
#pragma unroll
            for (int j = 0; j < 2; j++) {
                wmma::fragment<wmma::matrix_b, 16, 16, 16, __half, wmma::row_major> bf;
                wmma::load_matrix_sync(bf, &Bs[kc * LDB + nbase + j * 16], LDB);
#pragma unroll
                for (int i = 0; i < 2; i++)
                    wmma::mma_sync(acc[i][j], af[i], bf, acc[i][j]);
            }
        }
        __syncthreads();
    }

#pragma unroll
    for (int i = 0; i < 2; i++)
#pragma unroll
        for (int j = 0; j < 2; j++)
            wmma::store_matrix_sync(&ep[(mbase + i * 16) * BN + nbase + j * 16], acc[i][j], BN, wmma::mem_row_major);
    __syncthreads();
#pragma unroll
    for (int idx = tid; idx < 2048; idx += 256) {
        int row = idx >> 4, c4 = idx & 15;
        if (m0 + row < cnt)
            *(float4*)(d_y + (size_t)(off + m0 + row) * H + n0 + c4 * 4) = *(float4*)&ep[row * BN + c4 * 4];
    }
}

// ---------------- combine ----------------
__global__ __launch_bounds__(256) void combine_kernel(float* __restrict__ out) {
    int t = blockIdx.x;
    int p0 = d_token_pair[t * 4 + 0], p1 = d_token_pair[t * 4 + 1];
    int p2 = d_token_pair[t * 4 + 2], p3 = d_token_pair[t * 4 + 3];
    float w0 = d_pair_weight[p0], w1 = d_pair_weight[p1];
    float w2 = d_pair_weight[p2], w3 = d_pair_weight[p3];
    const float* y0 = d_y + (size_t)p0 * H;
    const float* y1 = d_y + (size_t)p1 * H;
    const float* y2 = d_y + (size_t)p2 * H;
    const float* y3 = d_y + (size_t)p3 * H;
    float* o = out + (size_t)t * H;
    for (int h = threadIdx.x; h < H; h += blockDim.x)
        o[h] = w0 * y0[h] + w1 * y1[h] + w2 * y2[h] + w3 * y3[h];
}

// ---------------- launch ----------------
extern "C" void kernel_launch(void* const* d_in, const int* in_sizes, int n_in,
                              void* d_out, int out_size) {
    const float* x      = (const float*)d_in[0];
    const float* gate_w = (const float*)d_in[1];
    const float* swg    = (const float*)d_in[2];
    const float* swu    = (const float*)d_in[3];
    const float* swd    = (const float*)d_in[4];
    const float* wg     = (const float*)d_in[5];
    const float* wu     = (const float*)d_in[6];
    const float* wd     = (const float*)d_in[7];
    float* out = (float*)d_out;

    cudaFuncSetAttribute(up_kernel,   cudaFuncAttributeMaxDynamicSharedMemorySize, UP_SMEM);
    cudaFuncSetAttribute(down_kernel, cudaFuncAttributeMaxDynamicSharedMemorySize, DN_SMEM);

    convert_all_kernel<<<4096, 256>>>((const float4*)wg, (const float4*)wu, (const float4*)wd,
                                      (const float4*)swg, (const float4*)swu, (const float4*)swd);

    init_kernel<<<1, 32>>>();
    router_kernel<<<NTOK / 8, 256>>>(x, gate_w);
    scan_kernel<<<1, 32>>>();
    build_pairs_kernel<<<NTOK / 256, 256>>>();
    gather_kernel<<<NPAIR, 192>>>(x);

    dim3 gUp(IDIM / BN, NTOK / BM, NEXP);     // (48, 16, 18)
    up_kernel<<<gUp, 256, UP_SMEM>>>();

    dim3 gDown(H / BN, NTOK / BM, NEXP);      // (12, 16, 18)
    down_kernel<<<gDown, 256, DN_SMEM>>>();

    combine_kernel<<<NTOK, 256>>>(out);
}

// round 12
// speedup vs baseline: 4.7906x; 1.0096x over previous
#include <cuda_runtime.h>
#include <cuda_fp16.h>
#include <mma.h>
#include <math.h>
#include <stdint.h>

using namespace nvcuda;

#define H     768
#define IDIM  3072
#define NE    16
#define NS    2
#define NEXP  (NE + NS)
#define NTOK  2048
#define KSEL  2
#define NPAIR (NTOK * 4)
#define ROUTED_PAIRS (NTOK * KSEL)

#define BM  128
#define BN  64
#define BK  64
#define LDK 72
#define LDB 72

#define CONVDN_BLOCKS 512

// ---------------- persistent scratch ----------------
__device__ __half d_wg_h[(size_t)NE * H * IDIM];
__device__ __half d_wu_h[(size_t)NE * H * IDIM];
__device__ __half d_wd_h[(size_t)NE * IDIM * H];
__device__ __half d_sg_h[(size_t)NS * H * IDIM];
__device__ __half d_su_h[(size_t)NS * H * IDIM];
__device__ __half d_sd_h[(size_t)NS * IDIM * H];
__device__ __half d_xg[(size_t)NPAIR * H];
__device__ __half d_act[(size_t)NPAIR * IDIM];
__device__ float d_y[(size_t)NPAIR * H];
__device__ int   d_pair_token[NPAIR];
__device__ float d_pair_weight[NPAIR];
__device__ int   d_token_pair[NTOK * 4];
__device__ int   d_cnt[NE];
__device__ int   d_fill[NE];
__device__ int   d_off[NEXP + 1];
__device__ int   d_tok_e[NTOK * KSEL];
__device__ float d_tok_w[NTOK * KSEL];

// ---------------- helpers ----------------
__device__ __forceinline__ uint2 cvtH4(float4 v) {
    uint32_t a = (uint32_t)__half_as_ushort(__float2half_rn(v.x))
               | ((uint32_t)__half_as_ushort(__float2half_rn(v.y)) << 16);
    uint32_t b = (uint32_t)__half_as_ushort(__float2half_rn(v.z))
               | ((uint32_t)__half_as_ushort(__float2half_rn(v.w)) << 16);
    return make_uint2(a, b);
}

__device__ __forceinline__ uint32_t smem_u32(const void* p) {
    uint32_t a;
    asm("{ .reg .u64 t; cvta.to.shared.u64 t, %1; cvt.u32.u64 %0, t; }" : "=r"(a) : "l"(p));
    return a;
}
__device__ __forceinline__ void cp16(uint32_t d, const void* s) {
    asm volatile("cp.async.cg.shared.global [%0], [%1], 16;" :: "r"(d), "l"(s) : "memory");
}
#define CP_COMMIT() asm volatile("cp.async.commit_group;" ::: "memory")
template<int N> __device__ __forceinline__ void cp_wait() {
    asm volatile("cp.async.wait_group %0;" :: "n"(N) : "memory");
}

// ---------------- routing ----------------
__global__ void init_kernel() {
    int t = threadIdx.x;
    if (t < NE) { d_cnt[t] = 0; d_fill[t] = 0; }
}

__global__ __launch_bounds__(256) void router_kernel(const float* __restrict__ x,
                                                     const float* __restrict__ gw) {
    int warp = (blockIdx.x * blockDim.x + threadIdx.x) >> 5;
    int lane = threadIdx.x & 31;
    if (warp >= NTOK) return;
    const float* xr = x + (size_t)warp * H;
    float acc[NE];
#pragma unroll
    for (int e = 0; e < NE; e++) acc[e] = 0.f;
    for (int h = lane; h < H; h += 32) {
        float xv = xr[h];
#pragma unroll
        for (int e = 0; e < NE; e++) acc[e] += xv * gw[e * H + h];
    }
#pragma unroll
    for (int e = 0; e < NE; e++) {
#pragma unroll
        for (int o = 16; o > 0; o >>= 1) acc[e] += __shfl_xor_sync(0xFFFFFFFFu, acc[e], o);
    }
    if (lane == 0) {
        float mx = acc[0];
#pragma unroll
        for (int e = 1; e < NE; e++) mx = fmaxf(mx, acc[e]);
        float p[NE]; float s = 0.f;
#pragma unroll
        for (int e = 0; e < NE; e++) { p[e] = expf(acc[e] - mx); s += p[e]; }
        float inv = 1.f / s;
#pragma unroll
        for (int e = 0; e < NE; e++) p[e] *= inv;
        int e0 = 0; float w0 = p[0];
        int e1 = -1; float w1 = -1.f;
#pragma unroll
        for (int e = 1; e < NE; e++) {
            if (p[e] > w0) { e1 = e0; w1 = w0; e0 = e; w0 = p[e]; }
            else if (p[e] > w1) { e1 = e; w1 = p[e]; }
        }
        float denom = w0 + w1 + 1e-8f;
        d_tok_e[warp * 2 + 0] = e0;  d_tok_w[warp * 2 + 0] = w0 / denom;
        d_tok_e[warp * 2 + 1] = e1;  d_tok_w[warp * 2 + 1] = w1 / denom;
        atomicAdd(&d_cnt[e0], 1);
        atomicAdd(&d_cnt[e1], 1);
    }
}

// build pairs with fused local scan
__global__ void build_pairs_kernel() {
    int t = blockIdx.x * blockDim.x + threadIdx.x;
    if (t >= NTOK) return;
    int offs[NE];
    {
        int acc = 0;
#pragma unroll
        for (int e = 0; e < NE; e++) { offs[e] = acc; acc += d_cnt[e]; }
    }
    if (t == 0) {
#pragma unroll
        for (int e = 0; e < NE; e++) d_off[e] = offs[e];
        d_off[NE]     = ROUTED_PAIRS;
        d_off[NE + 1] = ROUTED_PAIRS + NTOK;
        d_off[NE + 2] = ROUTED_PAIRS + 2 * NTOK;
    }
#pragma unroll
    for (int k = 0; k < KSEL; k++) {
        int e = d_tok_e[t * 2 + k];
        float w = d_tok_w[t * 2 + k];
        int pos = offs[e] + atomicAdd(&d_fill[e], 1);
        d_pair_token[pos] = t;
        d_pair_weight[pos] = w;
        d_token_pair[t * 4 + k] = pos;
    }
#pragma unroll
    for (int s = 0; s < NS; s++) {
        int pos = ROUTED_PAIRS + s * NTOK + t;
        d_pair_token[pos] = t;
        d_pair_weight[pos] = 0.5f;
        d_token_pair[t * 4 + 2 + s] = pos;
    }
}

// ---------------- fused gather + up-weight conversion ----------------
// blocks [0, NPAIR): gather token rows; blocks [NPAIR, NPAIR+4096): convert wg/wu/sg/su
__global__ __launch_bounds__(192) void gather_convup_kernel(
    const float* __restrict__ x,
    const float4* __restrict__ wg,  const float4* __restrict__ wu,
    const float4* __restrict__ swg, const float4* __restrict__ swu) {
    if (blockIdx.x < NPAIR) {
        int p = blockIdx.x;
        int t = threadIdx.x;
        int tok = d_pair_token[p];
        float4 v = *(const float4*)(x + (size_t)tok * H + t * 4);
        *(uint2*)(d_xg + (size_t)p * H + t * 4) = cvtH4(v);
        return;
    }
    const int NR  = NE * H * IDIM / 4;
    const int NSH = NS * H * IDIM / 4;
    const int total = 2 * NR + 2 * NSH;
    int base = (blockIdx.x - NPAIR) * 192 + threadIdx.x;
    for (int i = base; i < total; i += 4096 * 192) {
        const float4* src; uint2* dst; int idx;
        if (i < NR)                { src = wg;  dst = (uint2*)d_wg_h; idx = i; }
        else if (i < 2 * NR)       { src = wu;  dst = (uint2*)d_wu_h; idx = i - NR; }
        else if (i < 2 * NR + NSH) { src = swg; dst = (uint2*)d_sg_h; idx = i - 2 * NR; }
        else                       { src = swu; dst = (uint2*)d_su_h; idx = i - 2 * NR - NSH; }
        dst[idx] = cvtH4(__ldg(src + idx));
    }
}

// ---------------- up/gate GEMM (z==0 slice converts down-weights) ----------------
#define ST_A   (BM * LDK * 2)            // 18432
#define ST_B1  (BK * LDB * 2)            // 9216
#define ST_UP  (ST_A + 2 * ST_B1)        // 36864
#define UP_SMEM (2 * ST_UP)              // 73728

__global__ __launch_bounds__(256) void up_kernel(const float4* __restrict__ wd,
                                                 const float4* __restrict__ swd) {
    int tid = threadIdx.x;

    if (blockIdx.z == 0) {
        // down-weight conversion slice: runs first, co-resident with GEMM blocks
        int bid = blockIdx.y * gridDim.x + blockIdx.x;
        if (bid < CONVDN_BLOCKS) {
            const int NR  = NE * IDIM * H / 4;
            const int NSH = NS * IDIM * H / 4;
            const int total = NR + NSH;
            for (int i = bid * 256 + tid; i < total; i += CONVDN_BLOCKS * 256) {
                const float4* src; uint2* dst; int idx;
                if (i < NR) { src = wd;  dst = (uint2*)d_wd_h; idx = i; }
                else        { src = swd; dst = (uint2*)d_sd_h; idx = i - NR; }
                dst[idx] = cvtH4(__ldg(src + idx));
            }
        }
        return;
    }

    int ez  = blockIdx.z - 1;
    int off = d_off[ez];
    int cnt = d_off[ez + 1] - off;
    int m0  = blockIdx.y * BM;
    if (m0 >= cnt) return;
    int n0  = blockIdx.x * BN;

    const __half* Bg;
    const __half* Bu;
    if (ez < NE) {
        size_t wo = (size_t)ez * H * IDIM;
        Bg = d_wg_h + wo; Bu = d_wu_h + wo;
    } else {
        size_t wo = (size_t)(ez - NE) * H * IDIM;
        Bg = d_sg_h + wo; Bu = d_su_h + wo;
    }

    extern __shared__ char smraw[];
    uint32_t sb = smem_u32(smraw);
    float* ep = (float*)smraw;

    int wid = tid >> 5;
    int mbase = (wid & 3) * 32;
    int nbase = (wid >> 2) * 32;

    wmma::fragment<wmma::accumulator, 16, 16, 16, float> accg[2][2], accu[2][2];
#pragma unroll
    for (int i = 0; i < 2; i++)
#pragma unroll
        for (int j = 0; j < 2; j++) { wmma::fill_fragment(accg[i][j], 0.f); wmma::fill_fragment(accu[i][j], 0.f); }

    auto load_stage = [&](int s, int k0) {
        uint32_t st = sb + s * ST_UP;
#pragma unroll
        for (int c = tid; c < 2048; c += 256) {
            if (c < 1024) {
                int row = c >> 3, q = c & 7;
                int pr = off + min(m0 + row, cnt - 1);
                const __half* src = d_xg + (size_t)pr * H + k0 + q * 8;
                cp16(st + row * (LDK * 2) + q * 16, src);
            } else {
                int b = c - 1024;
                int mat = b >> 9, r = (b >> 3) & 63, q = b & 7;
                const __half* src = (mat ? Bu : Bg) + (size_t)(k0 + r) * IDIM + n0 + q * 8;
                cp16(st + ST_A + mat * ST_B1 + r * (LDB * 2) + q * 16, src);
            }
        }
    };

    const int KT = H / BK;   // 12
    load_stage(0, 0);
    CP_COMMIT();

    for (int kt = 0; kt < KT; kt++) {
        if (kt + 1 < KT) { load_stage((kt + 1) & 1, (kt + 1) * BK); CP_COMMIT(); cp_wait<1>(); }
        else cp_wait<0>();
        __syncthreads();

        char* st = smraw + (kt & 1) * ST_UP;
        __half* As  = (__half*)st;
        __half* BGs = (__half*)(st + ST_A);
        __half* BUs = (__half*)(st + ST_A + ST_B1);

#pragma unroll
        for (int ks = 0; ks < BK / 16; ks++) {
            int kc = ks * 16;
            wmma::fragment<wmma::matrix_a, 16, 16, 16, __half, wmma::row_major> af[2];
#pragma unroll
            for (int i = 0; i < 2; i++)
                wmma::load_matrix_sync(af[i], &As[(mbase + i * 16) * LDK + kc], LDK);
#pragma unroll
            for (int j = 0; j < 2; j++) {
                wmma::fragment<wmma::matrix_b, 16, 16, 16, __half, wmma::row_major> bg, bu;
                wmma::load_matrix_sync(bg, &BGs[kc * LDB + nbase + j * 16], LDB);
                wmma::load_matrix_sync(bu, &BUs[kc * LDB + nbase + j * 16], LDB);
#pragma unroll
                for (int i = 0; i < 2; i++) {
                    wmma::mma_sync(accg[i][j], af[i], bg, accg[i][j]);
                    wmma::mma_sync(accu[i][j], af[i], bu, accu[i][j]);
                }
            }
        }
        __syncthreads();
    }

#pragma unroll
    for (int i = 0; i < 2; i++)
#pragma unroll
        for (int j = 0; j < 2; j++) {
#pragma unroll
            for (int e = 0; e < accg[i][j].num_elements; e++) {
                float g = accg[i][j].x[e];
                float u = accu[i][j].x[e];
                accg[i][j].x[e] = (g / (1.f + expf(-g))) * u;
            }
            wmma::store_matrix_sync(&ep[(mbase + i * 16) * BN + nbase + j * 16], accg[i][j], BN, wmma::mem_row_major);
        }
    __syncthreads();
#pragma unroll
    for (int idx = tid; idx < 2048; idx += 256) {
        int row = idx >> 4, c4 = idx & 15;
        if (m0 + row < cnt) {
            float4 v = *(float4*)&ep[row * BN + c4 * 4];
            *(uint2*)(d_act + (size_t)(off + m0 + row) * IDIM + n0 + c4 * 4) = cvtH4(v);
        }
    }
}

// ---------------- down GEMM ----------------
#define ST_DN (ST_A + ST_B1)            // 27648
#define EP_BYTES (BM * BN * 4)          // 32768
#define DN_SMEM ((2 * ST_DN) > EP_BYTES ? (2 * ST_DN) : EP_BYTES)   // 55296

__global__ __launch_bounds__(256) void down_kernel() {
    int ez  = blockIdx.z;
    int off = d_off[ez];
    int cnt = d_off[ez + 1] - off;
    int m0  = blockIdx.y * BM;
    if (m0 >= cnt) return;
    int n0  = blockIdx.x * BN;

    const __half* Bw = (ez < NE) ? d_wd_h + (size_t)ez * IDIM * H
                                 : d_sd_h + (size_t)(ez - NE) * IDIM * H;

    extern __shared__ char smraw[];
    uint32_t sb = smem_u32(smraw);
    float* ep = (float*)smraw;

    int tid = threadIdx.x, wid = tid >> 5;
    int mbase = (wid & 3) * 32;
    int nbase = (wid >> 2) * 32;

    wmma::fragment<wmma::accumulator, 16, 16, 16, float> acc[2][2];
#pragma unroll
    for (int i = 0; i < 2; i++)
#pragma unroll
        for (int j = 0; j < 2; j++) wmma::fill_fragment(acc[i][j], 0.f);

    auto load_stage = [&](int s, int k0) {
        uint32_t st = sb + s * ST_DN;
#pragma unroll
        for (int c = tid; c < 1536; c += 256) {
            if (c < 1024) {
                int row = c >> 3, q = c & 7;
                int pr = off + min(m0 + row, cnt - 1);
                const __half* src = d_act + (size_t)pr * IDIM + k0 + q * 8;
                cp16(st + row * (LDK * 2) + q * 16, src);
            } else {
                int b = c - 1024;
                int r = b >> 3, q = b & 7;
                const __half* src = Bw + (size_t)(k0 + r) * H + n0 + q * 8;
                cp16(st + ST_A + r * (LDB * 2) + q * 16, src);
            }
        }
    };

    const int KT = IDIM / BK;   // 48
    load_stage(0, 0);
    CP_COMMIT();

    for (int kt = 0; kt < KT; kt++) {
        if (kt + 1 < KT) { load_stage((kt + 1) & 1, (kt + 1) * BK); CP_COMMIT(); cp_wait<1>(); }
        else cp_wait<0>();
        __syncthreads();

        char* st = smraw + (kt & 1) * ST_DN;
        __half* As = (__half*)st;
        __half* Bs = (__half*)(st + ST_A);

#pragma unroll
        for (int ks = 0; ks < BK / 16; ks++) {
            int kc = ks * 16;
            wmma::fragment<wmma::matrix_a, 16, 16, 16, __half, wmma::row_major> af[2];
#pragma unroll
            for (int i = 0; i < 2; i++)
                wmma::load_matrix_sync(af[i], &As[(mbase + i * 16) * LDK + kc], LDK);
#pragma unroll
            for (int j = 0; j < 2; j++) {
                wmma::fragment<wmma::matrix_b, 16, 16, 16, __half, wmma::row_major> bf;
                wmma::load_matrix_sync(bf, &Bs[kc * LDB + nbase + j * 16], LDB);
#pragma unroll
                for (int i = 0; i < 2; i++)
                    wmma::mma_sync(acc[i][j], af[i], bf, acc[i][j]);
            }
        }
        __syncthreads();
    }

#pragma unroll
    for (int i = 0; i < 2; i++)
#pragma unroll
        for (int j = 0; j < 2; j++)
            wmma::store_matrix_sync(&ep[(mbase + i * 16) * BN + nbase + j * 16], acc[i][j], BN, wmma::mem_row_major);
    __syncthreads();
#pragma unroll
    for (int idx = tid; idx < 2048; idx += 256) {
        int row = idx >> 4, c4 = idx & 15;
        if (m0 + row < cnt)
            *(float4*)(d_y + (size_t)(off + m0 + row) * H + n0 + c4 * 4) = *(float4*)&ep[row * BN + c4 * 4];
    }
}

// ---------------- combine ----------------
__global__ __launch_bounds__(256) void combine_kernel(float* __restrict__ out) {
    int t = blockIdx.x;
    int p0 = d_token_pair[t * 4 + 0], p1 = d_token_pair[t * 4 + 1];
    int p2 = d_token_pair[t * 4 + 2], p3 = d_token_pair[t * 4 + 3];
    float w0 = d_pair_weight[p0], w1 = d_pair_weight[p1];
    float w2 = d_pair_weight[p2], w3 = d_pair_weight[p3];
    const float* y0 = d_y + (size_t)p0 * H;
    const float* y1 = d_y + (size_t)p1 * H;
    const float* y2 = d_y + (size_t)p2 * H;
    const float* y3 = d_y + (size_t)p3 * H;
    float* o = out + (size_t)t * H;
    for (int h = threadIdx.x; h < H; h += blockDim.x)
        o[h] = w0 * y0[h] + w1 * y1[h] + w2 * y2[h] + w3 * y3[h];
}

// ---------------- launch ----------------
extern "C" void kernel_launch(void* const* d_in, const int* in_sizes, int n_in,
                              void* d_out, int out_size) {
    const float* x      = (const float*)d_in[0];
    const float* gate_w = (const float*)d_in[1];
    const float* swg    = (const float*)d_in[2];
    const float* swu    = (const float*)d_in[3];
    const float* swd    = (const float*)d_in[4];
    const float* wg     = (const float*)d_in[5];
    const float* wu     = (const float*)d_in[6];
    const float* wd     = (const float*)d_in[7];
    float* out = (float*)d_out;

    cudaFuncSetAttribute(up_kernel,   cudaFuncAttributeMaxDynamicSharedMemorySize, UP_SMEM);
    cudaFuncSetAttribute(down_kernel, cudaFuncAttributeMaxDynamicSharedMemorySize, DN_SMEM);

    init_kernel<<<1, 32>>>();
    router_kernel<<<NTOK / 8, 256>>>(x, gate_w);
    build_pairs_kernel<<<NTOK / 256, 256>>>();

    // fused: gather token rows + convert up-weights (one launch)
    gather_convup_kernel<<<NPAIR + 4096, 192>>>(x,
        (const float4*)wg, (const float4*)wu, (const float4*)swg, (const float4*)swu);

    // up GEMM; z==0 slice converts down-weights concurrently
    dim3 gUp(IDIM / BN, NTOK / BM, NEXP + 1);   // (48, 16, 19)
    up_kernel<<<gUp, 256, UP_SMEM>>>((const float4*)wd, (const float4*)swd);

    dim3 gDown(H / BN, NTOK / BM, NEXP);        // (12, 16, 18)
    down_kernel<<<gDown, 256, DN_SMEM>>>();

    combine_kernel<<<NTOK, 256>>>(out);
}